// round 12
// baseline (speedup 1.0000x reference)
#include <cuda_runtime.h>
#include <cuda_bf16.h>
#include <math.h>
#include <stdint.h>

// Problem constants
#define BB   2
#define LL   2048
#define DD   1024
#define HH   16
#define KVH  4
#define HDIM 64
#define BL   (BB * LL)    // 4096

typedef unsigned long long ull;

// ---------------------------------------------------------------------------
// mma.sync / ldmatrix / cp.async helpers (baseline PTX ISA)
// ---------------------------------------------------------------------------
__device__ __forceinline__ uint32_t smem_u32(const void* p) {
    uint32_t a;
    asm("{ .reg .u64 t; cvta.to.shared.u64 t, %1; cvt.u32.u64 %0, t; }"
        : "=r"(a) : "l"(p));
    return a;
}
__device__ __forceinline__ void ldsm4(uint32_t addr, uint32_t* r) {
    asm volatile("ldmatrix.sync.aligned.m8n8.x4.shared.b16 {%0,%1,%2,%3}, [%4];"
                 : "=r"(r[0]), "=r"(r[1]), "=r"(r[2]), "=r"(r[3]) : "r"(addr));
}
__device__ __forceinline__ void ldsm4t(uint32_t addr, uint32_t* r) {
    asm volatile("ldmatrix.sync.aligned.m8n8.x4.trans.shared.b16 {%0,%1,%2,%3}, [%4];"
                 : "=r"(r[0]), "=r"(r[1]), "=r"(r[2]), "=r"(r[3]) : "r"(addr));
}
__device__ __forceinline__ void mma16816(float* d, const uint32_t* a,
                                         const uint32_t* b) {
    asm volatile(
        "mma.sync.aligned.m16n8k16.row.col.f32.bf16.bf16.f32 "
        "{%0,%1,%2,%3}, {%4,%5,%6,%7}, {%8,%9}, {%0,%1,%2,%3};"
        : "+f"(d[0]), "+f"(d[1]), "+f"(d[2]), "+f"(d[3])
        : "r"(a[0]), "r"(a[1]), "r"(a[2]), "r"(a[3]), "r"(b[0]), "r"(b[1]));
}
__device__ __forceinline__ void cp16(uint32_t dst, const void* src) {
    asm volatile("cp.async.cg.shared.global [%0], [%1], 16;"
                 :: "r"(dst), "l"(src) : "memory");
}
#define CP_COMMIT() asm volatile("cp.async.commit_group;" ::: "memory")
#define CP_WAIT2()  asm volatile("cp.async.wait_group 2;" ::: "memory")
#define CP_WAIT1()  asm volatile("cp.async.wait_group 1;" ::: "memory")
#define CP_WAIT0()  asm volatile("cp.async.wait_group 0;" ::: "memory")

__device__ __forceinline__ uint32_t packbf(float lo, float hi) {
    __nv_bfloat162 t = __floats2bfloat162_rn(lo, hi);
    return *(uint32_t*)&t;
}
__device__ __forceinline__ float bfhi(float v) {
    return __bfloat162float(__float2bfloat16(v));
}

// ---------------------------------------------------------------------------
// Scratch (__device__ globals — no allocations allowed)
// ---------------------------------------------------------------------------
__device__ __nv_bfloat16 g_xhi[BL * DD];
__device__ __nv_bfloat16 g_xlo[BL * DD];
__device__ __nv_bfloat16 g_ctxhi[BL * DD];
__device__ __nv_bfloat16 g_ctxlo[BL * DD];
__device__ __nv_bfloat16 g_wqt_h[DD * DD];
__device__ __nv_bfloat16 g_wqt_l[DD * DD];
__device__ __nv_bfloat16 g_wkvt_h[512 * DD];
__device__ __nv_bfloat16 g_wkvt_l[512 * DD];
__device__ __nv_bfloat16 g_wot_h[DD * DD];
__device__ __nv_bfloat16 g_wot_l[DD * DD];

__device__ __nv_bfloat16 g_qh[BL * DD];
__device__ __nv_bfloat16 g_ql[BL * DD];
__device__ __nv_bfloat16 g_kh[BL * 256];
__device__ __nv_bfloat16 g_kl[BL * 256];
__device__ __nv_bfloat16 g_vh[BL * 256];
__device__ __nv_bfloat16 g_vl[BL * 256];

__device__ float g_cos[LL * 32];
__device__ float g_sin[LL * 32];

// ---------------------------------------------------------------------------
// prep_x: x split (4096 blocks) + rope tables (256 blocks)
// ---------------------------------------------------------------------------
__global__ __launch_bounds__(256)
void prep_x(const float* __restrict__ x,
            __nv_bfloat16* __restrict__ xhi, __nv_bfloat16* __restrict__ xlo,
            float* __restrict__ ct, float* __restrict__ st) {
    const int bid = blockIdx.x;
    if (bid < 4096) {
        int i = bid * 256 + threadIdx.x;
        float4 v = ((const float4*)x)[i];
        float vv[4] = {v.x, v.y, v.z, v.w};
        __nv_bfloat16 h[4], l[4];
#pragma unroll
        for (int j = 0; j < 4; j++) {
            h[j] = __float2bfloat16(vv[j]);
            l[j] = __float2bfloat16(vv[j] - __bfloat162float(h[j]));
        }
        ((uint64_t*)xhi)[i] = *(uint64_t*)h;
        ((uint64_t*)xlo)[i] = *(uint64_t*)l;
    } else {
        int i = (bid - 4096) * 256 + threadIdx.x;
        int pos = i >> 5, j = i & 31;
        float inv = powf(10000.0f, -(float)j * (1.0f / 32.0f));
        float s, c;
        sincosf((float)pos * inv, &s, &c);
        ct[i] = c;
        st[i] = s;
    }
}

// ---------------------------------------------------------------------------
// prep_w: weight transposes+splits
// ---------------------------------------------------------------------------
__global__ __launch_bounds__(256)
void prep_w(const float* __restrict__ Wq, const float* __restrict__ Wk,
            const float* __restrict__ Wv, const float* __restrict__ Wo,
            __nv_bfloat16* __restrict__ wqh, __nv_bfloat16* __restrict__ wql,
            __nv_bfloat16* __restrict__ wkvh, __nv_bfloat16* __restrict__ wkvl,
            __nv_bfloat16* __restrict__ woh, __nv_bfloat16* __restrict__ wol) {
    __shared__ float t[32][33];
    int j = blockIdx.x;
    const float* W;
    __nv_bfloat16 *hiT, *loT;
    int Nd, rowoff = 0, bx, by;
    if (j < 1024) { W = Wq; hiT = wqh; loT = wql; Nd = 1024;
                    bx = j & 31; by = j >> 5; }
    else if (j < 1536) {
        int j2 = j - 1024;
        int z = j2 >> 8;
        int r = j2 & 255;
        bx = r & 7; by = r >> 3;
        Nd = 256;
        hiT = wkvh; loT = wkvl;
        if (z == 0) { W = Wk; }
        else        { W = Wv; rowoff = 256; }
    } else {
        int j2 = j - 1536;
        W = Wo; hiT = woh; loT = wol; Nd = 1024;
        bx = j2 & 31; by = j2 >> 5;
    }
    int n0 = bx << 5, k0 = by << 5;
    int tx = threadIdx.x & 31, ty = threadIdx.x >> 5;
    for (int r = ty; r < 32; r += 8)
        t[r][tx] = W[(size_t)(k0 + r) * Nd + n0 + tx];
    __syncthreads();
    for (int r = ty; r < 32; r += 8) {
        float v = t[tx][r];
        __nv_bfloat16 h = __float2bfloat16(v);
        size_t o = (size_t)(rowoff + n0 + r) * DD + k0 + tx;
        hiT[o] = h;
        loT[o] = __float2bfloat16(v - __bfloat162float(h));
    }
}

// ---------------------------------------------------------------------------
// QKV GEMM (mma.sync bf16x3) with fused RoPE + bf16 hi/lo split epilogue.
// ---------------------------------------------------------------------------
#define STG_BYTES 40960
#define SUB_BYTES 10240

__global__ __launch_bounds__(256, 2)
void gemm_qkv(const __nv_bfloat16* __restrict__ Ahi,
              const __nv_bfloat16* __restrict__ Alo,
              const __nv_bfloat16* __restrict__ Wqh,
              const __nv_bfloat16* __restrict__ Wql,
              const __nv_bfloat16* __restrict__ Wkvh,
              const __nv_bfloat16* __restrict__ Wkvl,
              __nv_bfloat16* __restrict__ qh, __nv_bfloat16* __restrict__ ql,
              __nv_bfloat16* __restrict__ kh, __nv_bfloat16* __restrict__ kl,
              __nv_bfloat16* __restrict__ vh, __nv_bfloat16* __restrict__ vl,
              const float* __restrict__ ct, const float* __restrict__ st) {
    extern __shared__ char sm[];
    const uint32_t smb = smem_u32(sm);
    const int K = DD;

    const int tid = threadIdx.x;
    const int lid = tid & 31;
    const int wid = tid >> 5;
    const int wm  = wid >> 1;
    const int wn  = wid & 1;
    const int row0 = blockIdx.y << 7;
    const int NCH = K >> 5;

    const bool isQ = (int)blockIdx.x < 8;
    const int col0 = isQ ? (blockIdx.x << 7) : (((int)blockIdx.x - 8) << 7);
    const __nv_bfloat16* Bhi = isQ ? Wqh : Wkvh;
    const __nv_bfloat16* Blo = isQ ? Wql : Wkvl;

    const __nv_bfloat16* srcbase[4] = {Ahi, Alo, Bhi, Blo};

    auto prefetch = [&](int c, int stage) {
#pragma unroll
        for (int it = 0; it < 8; it++) {
            int i = tid + (it << 8);
            int s = i >> 9;
            int j = i & 511;
            int r = j >> 2;
            int u = j & 3;
            int grow = (s < 2 ? row0 : col0) + r;
            const __nv_bfloat16* src =
                srcbase[s] + (size_t)grow * K + (c << 5) + (u << 3);
            uint32_t dst = smb + stage * STG_BYTES + s * SUB_BYTES
                         + r * 80 + (u << 4);
            cp16(dst, src);
        }
    };

    prefetch(0, 0); CP_COMMIT();
    prefetch(1, 1); CP_COMMIT();

    float acc[2][8][4];
#pragma unroll
    for (int a = 0; a < 2; a++)
#pragma unroll
        for (int b = 0; b < 8; b++)
#pragma unroll
            for (int d = 0; d < 4; d++) acc[a][b][d] = 0.0f;

    const uint32_t aoff = (uint32_t)((wm * 32 + (lid & 15)) * 80
                                     + ((lid >> 4) << 4));
    const uint32_t boff = (uint32_t)((wn * 64 + ((lid >> 4) << 3) + (lid & 7)) * 80
                                     + (((lid >> 3) & 1) << 4));

    for (int c = 0; c < NCH; c++) {
        CP_WAIT1();
        __syncthreads();

        const uint32_t sb = smb + (c & 1) * STG_BYTES;
        const uint32_t sa_h = sb;
        const uint32_t sa_l = sb + SUB_BYTES;
        const uint32_t sb_h = sb + 2 * SUB_BYTES;
        const uint32_t sb_l = sb + 3 * SUB_BYTES;

#pragma unroll
        for (int ks = 0; ks < 2; ks++) {
            uint32_t Ah[2][4], Al[2][4];
            ldsm4(sa_h + aoff + ks * 32, Ah[0]);
            ldsm4(sa_h + aoff + 16 * 80 + ks * 32, Ah[1]);
            ldsm4(sa_l + aoff + ks * 32, Al[0]);
            ldsm4(sa_l + aoff + 16 * 80 + ks * 32, Al[1]);
#pragma unroll
            for (int g = 0; g < 4; g++) {
                uint32_t Bh[4], Bl[4];
                ldsm4(sb_h + boff + g * (16 * 80) + ks * 32, Bh);
                ldsm4(sb_l + boff + g * (16 * 80) + ks * 32, Bl);
#pragma unroll
                for (int mi = 0; mi < 2; mi++) {
                    mma16816(acc[mi][2 * g],     Ah[mi], Bh);
                    mma16816(acc[mi][2 * g],     Ah[mi], Bl);
                    mma16816(acc[mi][2 * g],     Al[mi], Bh);
                    mma16816(acc[mi][2 * g + 1], Ah[mi], Bh + 2);
                    mma16816(acc[mi][2 * g + 1], Ah[mi], Bl + 2);
                    mma16816(acc[mi][2 * g + 1], Al[mi], Bh + 2);
                }
            }
        }
        __syncthreads();
        if (c + 2 < NCH) prefetch(c + 2, c & 1);
        CP_COMMIT();
    }

    // ---- fused epilogue: RoPE (Q,K) + hi/lo split -> bf16 outputs ----
    __nv_bfloat16 *dsth, *dstl;
    int ldd, dcol0;
    bool rope;
    if (isQ)            { dsth = qh; dstl = ql; ldd = 1024; dcol0 = col0; rope = true; }
    else if (col0 < 256){ dsth = kh; dstl = kl; ldd = 256;  dcol0 = col0; rope = true; }
    else                { dsth = vh; dstl = vl; ldd = 256;  dcol0 = col0 - 256; rope = false; }

    const int rbase = row0 + wm * 32 + (lid >> 2);
#pragma unroll
    for (int mi = 0; mi < 2; mi++) {
#pragma unroll
        for (int half = 0; half < 2; half++) {
            const int row = rbase + mi * 16 + half * 8;
            const int pos = row & (LL - 1);
            const int e0 = half * 2;
            if (rope) {
#pragma unroll
                for (int ni = 0; ni < 4; ni++) {
                    const int j0 = ni * 8 + ((lid & 3) << 1);
                    float c0 = ct[pos * 32 + j0],     s0 = st[pos * 32 + j0];
                    float c1 = ct[pos * 32 + j0 + 1], s1 = st[pos * 32 + j0 + 1];
                    float x1a = acc[mi][ni][e0],     x1b = acc[mi][ni][e0 + 1];
                    float x2a = acc[mi][ni + 4][e0], x2b = acc[mi][ni + 4][e0 + 1];
                    float y1a = x1a * c0 - x2a * s0;
                    float y2a = x2a * c0 + x1a * s0;
                    float y1b = x1b * c1 - x2b * s1;
                    float y2b = x2b * c1 + x1b * s1;
                    float h1a = bfhi(y1a), h1b = bfhi(y1b);
                    float h2a = bfhi(y2a), h2b = bfhi(y2b);
                    size_t o1 = (size_t)row * ldd + dcol0 + wn * 64 + j0;
                    size_t o2 = o1 + 32;
                    *(uint32_t*)&dsth[o1] = packbf(h1a, h1b);
                    *(uint32_t*)&dstl[o1] = packbf(y1a - h1a, y1b - h1b);
                    *(uint32_t*)&dsth[o2] = packbf(h2a, h2b);
                    *(uint32_t*)&dstl[o2] = packbf(y2a - h2a, y2b - h2b);
                }
            } else {
#pragma unroll
                for (int ni = 0; ni < 8; ni++) {
                    const int j0 = ni * 8 + ((lid & 3) << 1);
                    float xa = acc[mi][ni][e0], xb = acc[mi][ni][e0 + 1];
                    float ha = bfhi(xa), hb = bfhi(xb);
                    size_t o1 = (size_t)row * ldd + dcol0 + wn * 64 + j0;
                    *(uint32_t*)&dsth[o1] = packbf(ha, hb);
                    *(uint32_t*)&dstl[o1] = packbf(xa - ha, xb - hb);
                }
            }
        }
    }
}

// ---------------------------------------------------------------------------
// Plain tensor-core GEMM for the output projection (fp32 epilogue).
// ---------------------------------------------------------------------------
__global__ __launch_bounds__(256, 2)
void gemm_o(const __nv_bfloat16* __restrict__ Ahi,
            const __nv_bfloat16* __restrict__ Alo,
            const __nv_bfloat16* __restrict__ Bhi,
            const __nv_bfloat16* __restrict__ Blo,
            float* __restrict__ C, int K, int ldc) {
    extern __shared__ char sm[];
    const uint32_t smb = smem_u32(sm);

    const int tid = threadIdx.x;
    const int lid = tid & 31;
    const int wid = tid >> 5;
    const int wm  = wid >> 1;
    const int wn  = wid & 1;
    const int row0 = blockIdx.y << 7;
    const int col0 = blockIdx.x << 7;
    const int NCH = K >> 5;

    const __nv_bfloat16* srcbase[4] = {Ahi, Alo, Bhi, Blo};

    auto prefetch = [&](int c, int stage) {
#pragma unroll
        for (int it = 0; it < 8; it++) {
            int i = tid + (it << 8);
            int s = i >> 9;
            int j = i & 511;
            int r = j >> 2;
            int u = j & 3;
            int grow = (s < 2 ? row0 : col0) + r;
            const __nv_bfloat16* src =
                srcbase[s] + (size_t)grow * K + (c << 5) + (u << 3);
            uint32_t dst = smb + stage * STG_BYTES + s * SUB_BYTES
                         + r * 80 + (u << 4);
            cp16(dst, src);
        }
    };

    prefetch(0, 0); CP_COMMIT();
    prefetch(1, 1); CP_COMMIT();

    float acc[2][8][4];
#pragma unroll
    for (int a = 0; a < 2; a++)
#pragma unroll
        for (int b = 0; b < 8; b++)
#pragma unroll
            for (int d = 0; d < 4; d++) acc[a][b][d] = 0.0f;

    const uint32_t aoff = (uint32_t)((wm * 32 + (lid & 15)) * 80
                                     + ((lid >> 4) << 4));
    const uint32_t boff = (uint32_t)((wn * 64 + ((lid >> 4) << 3) + (lid & 7)) * 80
                                     + (((lid >> 3) & 1) << 4));

    for (int c = 0; c < NCH; c++) {
        CP_WAIT1();
        __syncthreads();

        const uint32_t sb = smb + (c & 1) * STG_BYTES;
        const uint32_t sa_h = sb;
        const uint32_t sa_l = sb + SUB_BYTES;
        const uint32_t sb_h = sb + 2 * SUB_BYTES;
        const uint32_t sb_l = sb + 3 * SUB_BYTES;

#pragma unroll
        for (int ks = 0; ks < 2; ks++) {
            uint32_t Ah[2][4], Al[2][4];
            ldsm4(sa_h + aoff + ks * 32, Ah[0]);
            ldsm4(sa_h + aoff + 16 * 80 + ks * 32, Ah[1]);
            ldsm4(sa_l + aoff + ks * 32, Al[0]);
            ldsm4(sa_l + aoff + 16 * 80 + ks * 32, Al[1]);
#pragma unroll
            for (int g = 0; g < 4; g++) {
                uint32_t Bh[4], Bl[4];
                ldsm4(sb_h + boff + g * (16 * 80) + ks * 32, Bh);
                ldsm4(sb_l + boff + g * (16 * 80) + ks * 32, Bl);
#pragma unroll
                for (int mi = 0; mi < 2; mi++) {
                    mma16816(acc[mi][2 * g],     Ah[mi], Bh);
                    mma16816(acc[mi][2 * g],     Ah[mi], Bl);
                    mma16816(acc[mi][2 * g],     Al[mi], Bh);
                    mma16816(acc[mi][2 * g + 1], Ah[mi], Bh + 2);
                    mma16816(acc[mi][2 * g + 1], Ah[mi], Bl + 2);
                    mma16816(acc[mi][2 * g + 1], Al[mi], Bh + 2);
                }
            }
        }
        __syncthreads();
        if (c + 2 < NCH) prefetch(c + 2, c & 1);
        CP_COMMIT();
    }

#pragma unroll
    for (int mi = 0; mi < 2; mi++) {
        int r0 = row0 + wm * 32 + mi * 16 + (lid >> 2);
#pragma unroll
        for (int ni = 0; ni < 8; ni++) {
            int cc = col0 + wn * 64 + ni * 8 + ((lid & 3) << 1);
            float2 v0; v0.x = acc[mi][ni][0]; v0.y = acc[mi][ni][1];
            float2 v1; v1.x = acc[mi][ni][2]; v1.y = acc[mi][ni][3];
            *(float2*)(C + (size_t)r0 * ldc + cc)       = v0;
            *(float2*)(C + (size_t)(r0 + 8) * ldc + cc) = v1;
        }
    }
}

// ---------------------------------------------------------------------------
// Tensor-core flash attention, analytic-max softmax, 3-stage KV ring,
// SINGLE barrier per tile. FIXED schedule vs round 11:
//   top of iter c: __syncthreads(); pf(c+2) -> stage (c+2)%3 (== stage read
//   in iter c-1, all readers past the barrier); CP_WAIT2 -> pf(c) complete;
//   compute on stage c%3. Write target is never the reading or in-flight
//   stage.
// ---------------------------------------------------------------------------
#define AST 144
#define KVSUB (64 * AST)
#define KVSTG (4 * KVSUB)          // 36864
#define QSUB  KVSTG
#define ATT_SMEM (3 * KVSTG)       // 110592

__global__ __launch_bounds__(256, 1)
void attn_mma(const __nv_bfloat16* __restrict__ qh, const __nv_bfloat16* __restrict__ ql,
              const __nv_bfloat16* __restrict__ kh, const __nv_bfloat16* __restrict__ kl,
              const __nv_bfloat16* __restrict__ vh, const __nv_bfloat16* __restrict__ vl,
              __nv_bfloat16* __restrict__ cthi, __nv_bfloat16* __restrict__ ctlo) {
    extern __shared__ char sm[];
    const uint32_t smb = smem_u32(sm);

    const int tid = threadIdx.x;
    const int lid = tid & 31;
    const int wid = tid >> 5;
    const int q0  = blockIdx.x << 8;
    const int h   = blockIdx.y;
    const int b   = blockIdx.z;
    const int kvh2 = h >> 2;

    const float slope = exp2f(-0.5f * (float)(h + 1));
    const float scale = 0.125f;

    // ---- stage Q (hi @ stage0, lo @ stage1) through the KV ring ----
#pragma unroll
    for (int t = 0; t < 16; t++) {
        int i = tid + (t << 8);
        int s = i >> 11;
        int j = i & 2047;
        int r = j >> 3;
        int u = j & 7;
        const __nv_bfloat16* src =
            (s ? ql : qh) + (size_t)(b * LL + q0 + r) * 1024 + h * 64 + (u << 3);
        cp16(smb + s * QSUB + r * AST + (u << 4), src);
    }
    CP_COMMIT();
    CP_WAIT0();
    __syncthreads();

    // ---- Q fragments for both 16-row blocks -> registers ----
    uint32_t AQh[2][4][4], AQl[2][4][4];
#pragma unroll
    for (int bl = 0; bl < 2; bl++) {
        uint32_t qaddr = (uint32_t)((wid * 32 + bl * 16 + (lid & 15)) * AST
                                    + ((lid >> 4) << 4));
#pragma unroll
        for (int kt = 0; kt < 4; kt++) {
            ldsm4(smb + qaddr + kt * 32, AQh[bl][kt]);
            ldsm4(smb + QSUB + qaddr + kt * 32, AQl[bl][kt]);
        }
    }
    __syncthreads();   // all warps done reading Q before KV ring overwrites

    // ---- KV ring (3 stages, 2 pre-filled) ----
    const __nv_bfloat16* kvsrc[4] = {kh, kl, vh, vl};
    auto pf = [&](int c, int st) {
#pragma unroll
        for (int t = 0; t < 8; t++) {
            int i = tid + (t << 8);
            int s = i >> 9;
            int j = i & 511;
            int r = j >> 3;
            int u = j & 7;
            const __nv_bfloat16* src =
                kvsrc[s] + (size_t)(b * LL + (c << 6) + r) * 256 + kvh2 * 64 + (u << 3);
            cp16(smb + st * KVSTG + s * KVSUB + r * AST + (u << 4), src);
        }
    };
    pf(0, 0); CP_COMMIT();
    pf(1, 1); CP_COMMIT();

    const uint32_t kaddr = (uint32_t)((((lid >> 4) << 3) + (lid & 7)) * AST
                                      + (((lid >> 3) & 1) << 4));
    const uint32_t vaddr = (uint32_t)((lid & 15) * AST + ((lid >> 4) << 4));

    float o[2][8][4];
    float lsum[2][2];
#pragma unroll
    for (int bl = 0; bl < 2; bl++) {
#pragma unroll
        for (int i = 0; i < 8; i++)
#pragma unroll
            for (int e = 0; e < 4; e++) o[bl][i][e] = 0.0f;
        lsum[bl][0] = 0.0f; lsum[bl][1] = 0.0f;
    }

    const int NTILES = LL / 64;

    int rdstage = 0;   // = c % 3
    int wrstage = 2;   // = (c+2) % 3
    for (int c = 0; c < NTILES; c++) {
        __syncthreads();   // single barrier: readers of wrstage (iter c-1) done

        // prefetch tile c+2 into stage (c+2)%3 (not reading, not in flight)
        if (c + 2 < NTILES) pf(c + 2, wrstage);
        CP_COMMIT();
        CP_WAIT2();        // pf(c) complete (pf(c+1), pf(c+2) may be in flight)

        const uint32_t sb  = smb + rdstage * KVSTG;
        const uint32_t skh = sb;
        const uint32_t skl = sb + KVSUB;
        const uint32_t svh = sb + 2 * KVSUB;
        const uint32_t svl = sb + 3 * KVSUB;

        float S[2][8][4];
#pragma unroll
        for (int bl = 0; bl < 2; bl++)
#pragma unroll
            for (int i = 0; i < 8; i++)
#pragma unroll
                for (int e = 0; e < 4; e++) S[bl][i][e] = 0.0f;

#pragma unroll
        for (int g = 0; g < 4; g++) {
#pragma unroll
            for (int ks = 0; ks < 4; ks++) {
                uint32_t Bh[4], Bl[4];
                uint32_t base = (g << 4) * AST + kaddr + (ks << 5);
                ldsm4(skh + base, Bh);
                ldsm4(skl + base, Bl);
#pragma unroll
                for (int bl = 0; bl < 2; bl++) {
                    mma16816(S[bl][2 * g],     AQh[bl][ks], Bh);
                    mma16816(S[bl][2 * g],     AQh[bl][ks], Bl);
                    mma16816(S[bl][2 * g],     AQl[bl][ks], Bh);
                    mma16816(S[bl][2 * g + 1], AQh[bl][ks], Bh + 2);
                    mma16816(S[bl][2 * g + 1], AQh[bl][ks], Bl + 2);
                    mma16816(S[bl][2 * g + 1], AQl[bl][ks], Bh + 2);
                }
            }
        }

        // ---- softmax with analytic max bound (q-independent bias) ----
        uint32_t PAh[2][4][4], PAl[2][4][4];
        const float bias00 =
            slope * ((float)((c << 6) + 2 * (lid & 3)) - 2047.0f) - 8.0f;
#pragma unroll
        for (int bl = 0; bl < 2; bl++) {
#pragma unroll
            for (int nt = 0; nt < 8; nt++) {
                const float be = bias00 + slope * (float)(nt << 3);
                const float bo = be + slope;
                float p0 = __expf(fmaf(S[bl][nt][0], scale, be));
                float p1 = __expf(fmaf(S[bl][nt][1], scale, bo));
                float p2 = __expf(fmaf(S[bl][nt][2], scale, be));
                float p3 = __expf(fmaf(S[bl][nt][3], scale, bo));
                lsum[bl][0] += p0 + p1;
                lsum[bl][1] += p2 + p3;
                S[bl][nt][0] = p0; S[bl][nt][1] = p1;
                S[bl][nt][2] = p2; S[bl][nt][3] = p3;
            }

#pragma unroll
            for (int kt = 0; kt < 4; kt++) {
                float p00 = S[bl][2 * kt][0],     p01 = S[bl][2 * kt][1];
                float p02 = S[bl][2 * kt][2],     p03 = S[bl][2 * kt][3];
                float p10 = S[bl][2 * kt + 1][0], p11 = S[bl][2 * kt + 1][1];
                float p12 = S[bl][2 * kt + 1][2], p13 = S[bl][2 * kt + 1][3];
                float h00 = bfhi(p00), h01 = bfhi(p01), h02 = bfhi(p02), h03 = bfhi(p03);
                float h10 = bfhi(p10), h11 = bfhi(p11), h12 = bfhi(p12), h13 = bfhi(p13);
                PAh[bl][kt][0] = packbf(h00, h01);
                PAh[bl][kt][1] = packbf(h02, h03);
                PAh[bl][kt][2] = packbf(h10, h11);
                PAh[bl][kt][3] = packbf(h12, h13);
                PAl[bl][kt][0] = packbf(p00 - h00, p01 - h01);
                PAl[bl][kt][1] = packbf(p02 - h02, p03 - h03);
                PAl[bl][kt][2] = packbf(p10 - h10, p11 - h11);
                PAl[bl][kt][3] = packbf(p12 - h12, p13 - h13);
            }
        }

        // ---- O += P @ V ----
#pragma unroll
        for (int dg = 0; dg < 4; dg++) {
#pragma unroll
            for (int kt = 0; kt < 4; kt++) {
                uint32_t Bvh[4], Bvl[4];
                uint32_t base = (kt << 4) * AST + vaddr + (dg << 5);
                ldsm4t(svh + base, Bvh);
                ldsm4t(svl + base, Bvl);
#pragma unroll
                for (int bl = 0; bl < 2; bl++) {
                    mma16816(o[bl][2 * dg],     PAh[bl][kt], Bvh);
                    mma16816(o[bl][2 * dg],     PAh[bl][kt], Bvl);
                    mma16816(o[bl][2 * dg],     PAl[bl][kt], Bvh);
                    mma16816(o[bl][2 * dg + 1], PAh[bl][kt], Bvh + 2);
                    mma16816(o[bl][2 * dg + 1], PAh[bl][kt], Bvl + 2);
                    mma16816(o[bl][2 * dg + 1], PAl[bl][kt], Bvh + 2);
                }
            }
        }

        rdstage++; if (rdstage == 3) rdstage = 0;
        wrstage++; if (wrstage == 3) wrstage = 0;
    }

    // ---- epilogue: reduce lsum across quad lanes, normalize, split ----
#pragma unroll
    for (int bl = 0; bl < 2; bl++) {
#pragma unroll
        for (int r = 0; r < 2; r++) {
            lsum[bl][r] += __shfl_xor_sync(0xffffffffu, lsum[bl][r], 1);
            lsum[bl][r] += __shfl_xor_sync(0xffffffffu, lsum[bl][r], 2);
        }
        float inv0 = 1.0f / lsum[bl][0];
        float inv1 = 1.0f / lsum[bl][1];
        const int r0 = b * LL + q0 + wid * 32 + bl * 16 + (lid >> 2);
#pragma unroll
        for (int nt = 0; nt < 8; nt++) {
            int cc = h * 64 + nt * 8 + ((lid & 3) << 1);
            float v0 = o[bl][nt][0] * inv0, v1 = o[bl][nt][1] * inv0;
            float v2 = o[bl][nt][2] * inv1, v3 = o[bl][nt][3] * inv1;
            float h0 = bfhi(v0), h1 = bfhi(v1), h2 = bfhi(v2), h3 = bfhi(v3);
            size_t oa = (size_t)r0 * 1024 + cc;
            size_t ob = (size_t)(r0 + 8) * 1024 + cc;
            *(uint32_t*)&cthi[oa] = packbf(h0, h1);
            *(uint32_t*)&ctlo[oa] = packbf(v0 - h0, v1 - h1);
            *(uint32_t*)&cthi[ob] = packbf(h2, h3);
            *(uint32_t*)&ctlo[ob] = packbf(v2 - h2, v3 - h3);
        }
    }
}

// ---------------------------------------------------------------------------
// kernel_launch: 0 prep_x  1 prep_w  2 gemm_qkv  3 attn_mma(capture)  4 gemm_o
// ---------------------------------------------------------------------------
extern "C" void kernel_launch(void* const* d_in, const int* in_sizes, int n_in,
                              void* d_out, int out_size) {
    const float* x  = (const float*)d_in[0];
    const float* Wq = (const float*)d_in[1];
    const float* Wk = (const float*)d_in[2];
    const float* Wv = (const float*)d_in[3];
    const float* Wo = (const float*)d_in[4];
    float* out = (float*)d_out;

    __nv_bfloat16 *xhi, *xlo, *cthi, *ctlo;
    __nv_bfloat16 *wqh, *wql, *wkvh, *wkvl, *woh, *wol;
    __nv_bfloat16 *aqh, *aql, *akh, *akl, *avh, *avl;
    float *ct, *st;
    cudaGetSymbolAddress((void**)&xhi,  g_xhi);
    cudaGetSymbolAddress((void**)&xlo,  g_xlo);
    cudaGetSymbolAddress((void**)&cthi, g_ctxhi);
    cudaGetSymbolAddress((void**)&ctlo, g_ctxlo);
    cudaGetSymbolAddress((void**)&wqh,  g_wqt_h);
    cudaGetSymbolAddress((void**)&wql,  g_wqt_l);
    cudaGetSymbolAddress((void**)&wkvh, g_wkvt_h);
    cudaGetSymbolAddress((void**)&wkvl, g_wkvt_l);
    cudaGetSymbolAddress((void**)&woh,  g_wot_h);
    cudaGetSymbolAddress((void**)&wol,  g_wot_l);
    cudaGetSymbolAddress((void**)&aqh,  g_qh);
    cudaGetSymbolAddress((void**)&aql,  g_ql);
    cudaGetSymbolAddress((void**)&akh,  g_kh);
    cudaGetSymbolAddress((void**)&akl,  g_kl);
    cudaGetSymbolAddress((void**)&avh,  g_vh);
    cudaGetSymbolAddress((void**)&avl,  g_vl);
    cudaGetSymbolAddress((void**)&ct,   g_cos);
    cudaGetSymbolAddress((void**)&st,   g_sin);

    const int smem_gemm = 2 * STG_BYTES;
    cudaFuncSetAttribute(gemm_qkv, cudaFuncAttributeMaxDynamicSharedMemorySize,
                         smem_gemm);
    cudaFuncSetAttribute(gemm_o, cudaFuncAttributeMaxDynamicSharedMemorySize,
                         smem_gemm);
    cudaFuncSetAttribute(attn_mma, cudaFuncAttributeMaxDynamicSharedMemorySize,
                         ATT_SMEM);

    dim3 blk(256);

    // 0: x split + rope tables
    prep_x<<<4096 + 256, blk>>>(x, xhi, xlo, ct, st);
    // 1: weight transposes+splits
    prep_w<<<2560, blk>>>(Wq, Wk, Wv, Wo, wqh, wql, wkvh, wkvl, woh, wol);

    // 2: QKV projection with fused RoPE + bf16 split epilogue
    gemm_qkv<<<dim3(12, BL / 128), blk, smem_gemm>>>(
        xhi, xlo, wqh, wql, wkvh, wkvl, aqh, aql, akh, akl, avh, avl, ct, st);

    // 3: tensor-core attention (analytic-max softmax)  <-- ncu capture slot
    attn_mma<<<dim3(LL / 256, HH, BB), blk, ATT_SMEM>>>(
        aqh, aql, akh, akl, avh, avl, cthi, ctlo);

    // 4: output projection
    gemm_o<<<dim3(8, BL / 128), blk, smem_gemm>>>(
        cthi, ctlo, woh, wol, out, DD, DD);
}

// round 13
// speedup vs baseline: 1.0297x; 1.0297x over previous
#include <cuda_runtime.h>
#include <cuda_bf16.h>
#include <math.h>
#include <stdint.h>

// Problem constants
#define BB   2
#define LL   2048
#define DD   1024
#define HH   16
#define KVH  4
#define HDIM 64
#define BL   (BB * LL)    // 4096

typedef unsigned long long ull;

// ---------------------------------------------------------------------------
// mma.sync / ldmatrix / cp.async helpers (baseline PTX ISA)
// ---------------------------------------------------------------------------
__device__ __forceinline__ uint32_t smem_u32(const void* p) {
    uint32_t a;
    asm("{ .reg .u64 t; cvta.to.shared.u64 t, %1; cvt.u32.u64 %0, t; }"
        : "=r"(a) : "l"(p));
    return a;
}
__device__ __forceinline__ void ldsm4(uint32_t addr, uint32_t* r) {
    asm volatile("ldmatrix.sync.aligned.m8n8.x4.shared.b16 {%0,%1,%2,%3}, [%4];"
                 : "=r"(r[0]), "=r"(r[1]), "=r"(r[2]), "=r"(r[3]) : "r"(addr));
}
__device__ __forceinline__ void ldsm4t(uint32_t addr, uint32_t* r) {
    asm volatile("ldmatrix.sync.aligned.m8n8.x4.trans.shared.b16 {%0,%1,%2,%3}, [%4];"
                 : "=r"(r[0]), "=r"(r[1]), "=r"(r[2]), "=r"(r[3]) : "r"(addr));
}
__device__ __forceinline__ void mma16816(float* d, const uint32_t* a,
                                         const uint32_t* b) {
    asm volatile(
        "mma.sync.aligned.m16n8k16.row.col.f32.bf16.bf16.f32 "
        "{%0,%1,%2,%3}, {%4,%5,%6,%7}, {%8,%9}, {%0,%1,%2,%3};"
        : "+f"(d[0]), "+f"(d[1]), "+f"(d[2]), "+f"(d[3])
        : "r"(a[0]), "r"(a[1]), "r"(a[2]), "r"(a[3]), "r"(b[0]), "r"(b[1]));
}
__device__ __forceinline__ void cp16(uint32_t dst, const void* src) {
    asm volatile("cp.async.cg.shared.global [%0], [%1], 16;"
                 :: "r"(dst), "l"(src) : "memory");
}
#define CP_COMMIT() asm volatile("cp.async.commit_group;" ::: "memory")
#define CP_WAIT1()  asm volatile("cp.async.wait_group 1;" ::: "memory")
#define CP_WAIT0()  asm volatile("cp.async.wait_group 0;" ::: "memory")

__device__ __forceinline__ uint32_t packbf(float lo, float hi) {
    __nv_bfloat162 t = __floats2bfloat162_rn(lo, hi);
    return *(uint32_t*)&t;
}
__device__ __forceinline__ float bfhi(float v) {
    return __bfloat162float(__float2bfloat16(v));
}

// ---------------------------------------------------------------------------
// Scratch (__device__ globals — no allocations allowed)
// ---------------------------------------------------------------------------
__device__ __nv_bfloat16 g_xhi[BL * DD];
__device__ __nv_bfloat16 g_xlo[BL * DD];
__device__ __nv_bfloat16 g_ctxhi[BL * DD];
__device__ __nv_bfloat16 g_ctxlo[BL * DD];
__device__ __nv_bfloat16 g_wqt_h[DD * DD];
__device__ __nv_bfloat16 g_wqt_l[DD * DD];
__device__ __nv_bfloat16 g_wkvt_h[512 * DD];
__device__ __nv_bfloat16 g_wkvt_l[512 * DD];
__device__ __nv_bfloat16 g_wot_h[DD * DD];
__device__ __nv_bfloat16 g_wot_l[DD * DD];

__device__ __nv_bfloat16 g_qh[BL * DD];
__device__ __nv_bfloat16 g_ql[BL * DD];
__device__ __nv_bfloat16 g_kh[BL * 256];
__device__ __nv_bfloat16 g_kl[BL * 256];
__device__ __nv_bfloat16 g_vh[BL * 256];
__device__ __nv_bfloat16 g_vl[BL * 256];

__device__ float g_cos[LL * 32];
__device__ float g_sin[LL * 32];

// ---------------------------------------------------------------------------
// prep_x: x split (4096 blocks) + rope tables (256 blocks)
// ---------------------------------------------------------------------------
__global__ __launch_bounds__(256)
void prep_x(const float* __restrict__ x,
            __nv_bfloat16* __restrict__ xhi, __nv_bfloat16* __restrict__ xlo,
            float* __restrict__ ct, float* __restrict__ st) {
    const int bid = blockIdx.x;
    if (bid < 4096) {
        int i = bid * 256 + threadIdx.x;
        float4 v = ((const float4*)x)[i];
        float vv[4] = {v.x, v.y, v.z, v.w};
        __nv_bfloat16 h[4], l[4];
#pragma unroll
        for (int j = 0; j < 4; j++) {
            h[j] = __float2bfloat16(vv[j]);
            l[j] = __float2bfloat16(vv[j] - __bfloat162float(h[j]));
        }
        ((uint64_t*)xhi)[i] = *(uint64_t*)h;
        ((uint64_t*)xlo)[i] = *(uint64_t*)l;
    } else {
        int i = (bid - 4096) * 256 + threadIdx.x;
        int pos = i >> 5, j = i & 31;
        float inv = powf(10000.0f, -(float)j * (1.0f / 32.0f));
        float s, c;
        sincosf((float)pos * inv, &s, &c);
        ct[i] = c;
        st[i] = s;
    }
}

// ---------------------------------------------------------------------------
// prep_w: weight transposes+splits
// ---------------------------------------------------------------------------
__global__ __launch_bounds__(256)
void prep_w(const float* __restrict__ Wq, const float* __restrict__ Wk,
            const float* __restrict__ Wv, const float* __restrict__ Wo,
            __nv_bfloat16* __restrict__ wqh, __nv_bfloat16* __restrict__ wql,
            __nv_bfloat16* __restrict__ wkvh, __nv_bfloat16* __restrict__ wkvl,
            __nv_bfloat16* __restrict__ woh, __nv_bfloat16* __restrict__ wol) {
    __shared__ float t[32][33];
    int j = blockIdx.x;
    const float* W;
    __nv_bfloat16 *hiT, *loT;
    int Nd, rowoff = 0, bx, by;
    if (j < 1024) { W = Wq; hiT = wqh; loT = wql; Nd = 1024;
                    bx = j & 31; by = j >> 5; }
    else if (j < 1536) {
        int j2 = j - 1024;
        int z = j2 >> 8;
        int r = j2 & 255;
        bx = r & 7; by = r >> 3;
        Nd = 256;
        hiT = wkvh; loT = wkvl;
        if (z == 0) { W = Wk; }
        else        { W = Wv; rowoff = 256; }
    } else {
        int j2 = j - 1536;
        W = Wo; hiT = woh; loT = wol; Nd = 1024;
        bx = j2 & 31; by = j2 >> 5;
    }
    int n0 = bx << 5, k0 = by << 5;
    int tx = threadIdx.x & 31, ty = threadIdx.x >> 5;
    for (int r = ty; r < 32; r += 8)
        t[r][tx] = W[(size_t)(k0 + r) * Nd + n0 + tx];
    __syncthreads();
    for (int r = ty; r < 32; r += 8) {
        float v = t[tx][r];
        __nv_bfloat16 h = __float2bfloat16(v);
        size_t o = (size_t)(rowoff + n0 + r) * DD + k0 + tx;
        hiT[o] = h;
        loT[o] = __float2bfloat16(v - __bfloat162float(h));
    }
}

// ---------------------------------------------------------------------------
// QKV GEMM (mma.sync bf16x3) with fused RoPE + bf16 hi/lo split epilogue.
// ---------------------------------------------------------------------------
#define STG_BYTES 40960
#define SUB_BYTES 10240

__global__ __launch_bounds__(256, 2)
void gemm_qkv(const __nv_bfloat16* __restrict__ Ahi,
              const __nv_bfloat16* __restrict__ Alo,
              const __nv_bfloat16* __restrict__ Wqh,
              const __nv_bfloat16* __restrict__ Wql,
              const __nv_bfloat16* __restrict__ Wkvh,
              const __nv_bfloat16* __restrict__ Wkvl,
              __nv_bfloat16* __restrict__ qh, __nv_bfloat16* __restrict__ ql,
              __nv_bfloat16* __restrict__ kh, __nv_bfloat16* __restrict__ kl,
              __nv_bfloat16* __restrict__ vh, __nv_bfloat16* __restrict__ vl,
              const float* __restrict__ ct, const float* __restrict__ st) {
    extern __shared__ char sm[];
    const uint32_t smb = smem_u32(sm);
    const int K = DD;

    const int tid = threadIdx.x;
    const int lid = tid & 31;
    const int wid = tid >> 5;
    const int wm  = wid >> 1;
    const int wn  = wid & 1;
    const int row0 = blockIdx.y << 7;
    const int NCH = K >> 5;

    const bool isQ = (int)blockIdx.x < 8;
    const int col0 = isQ ? (blockIdx.x << 7) : (((int)blockIdx.x - 8) << 7);
    const __nv_bfloat16* Bhi = isQ ? Wqh : Wkvh;
    const __nv_bfloat16* Blo = isQ ? Wql : Wkvl;

    const __nv_bfloat16* srcbase[4] = {Ahi, Alo, Bhi, Blo};

    auto prefetch = [&](int c, int stage) {
#pragma unroll
        for (int it = 0; it < 8; it++) {
            int i = tid + (it << 8);
            int s = i >> 9;
            int j = i & 511;
            int r = j >> 2;
            int u = j & 3;
            int grow = (s < 2 ? row0 : col0) + r;
            const __nv_bfloat16* src =
                srcbase[s] + (size_t)grow * K + (c << 5) + (u << 3);
            uint32_t dst = smb + stage * STG_BYTES + s * SUB_BYTES
                         + r * 80 + (u << 4);
            cp16(dst, src);
        }
    };

    prefetch(0, 0); CP_COMMIT();
    prefetch(1, 1); CP_COMMIT();

    float acc[2][8][4];
#pragma unroll
    for (int a = 0; a < 2; a++)
#pragma unroll
        for (int b = 0; b < 8; b++)
#pragma unroll
            for (int d = 0; d < 4; d++) acc[a][b][d] = 0.0f;

    const uint32_t aoff = (uint32_t)((wm * 32 + (lid & 15)) * 80
                                     + ((lid >> 4) << 4));
    const uint32_t boff = (uint32_t)((wn * 64 + ((lid >> 4) << 3) + (lid & 7)) * 80
                                     + (((lid >> 3) & 1) << 4));

    for (int c = 0; c < NCH; c++) {
        CP_WAIT1();
        __syncthreads();

        const uint32_t sb = smb + (c & 1) * STG_BYTES;
        const uint32_t sa_h = sb;
        const uint32_t sa_l = sb + SUB_BYTES;
        const uint32_t sb_h = sb + 2 * SUB_BYTES;
        const uint32_t sb_l = sb + 3 * SUB_BYTES;

#pragma unroll
        for (int ks = 0; ks < 2; ks++) {
            uint32_t Ah[2][4], Al[2][4];
            ldsm4(sa_h + aoff + ks * 32, Ah[0]);
            ldsm4(sa_h + aoff + 16 * 80 + ks * 32, Ah[1]);
            ldsm4(sa_l + aoff + ks * 32, Al[0]);
            ldsm4(sa_l + aoff + 16 * 80 + ks * 32, Al[1]);
#pragma unroll
            for (int g = 0; g < 4; g++) {
                uint32_t Bh[4], Bl[4];
                ldsm4(sb_h + boff + g * (16 * 80) + ks * 32, Bh);
                ldsm4(sb_l + boff + g * (16 * 80) + ks * 32, Bl);
#pragma unroll
                for (int mi = 0; mi < 2; mi++) {
                    mma16816(acc[mi][2 * g],     Ah[mi], Bh);
                    mma16816(acc[mi][2 * g],     Ah[mi], Bl);
                    mma16816(acc[mi][2 * g],     Al[mi], Bh);
                    mma16816(acc[mi][2 * g + 1], Ah[mi], Bh + 2);
                    mma16816(acc[mi][2 * g + 1], Ah[mi], Bl + 2);
                    mma16816(acc[mi][2 * g + 1], Al[mi], Bh + 2);
                }
            }
        }
        __syncthreads();
        if (c + 2 < NCH) prefetch(c + 2, c & 1);
        CP_COMMIT();
    }

    // ---- fused epilogue: RoPE (Q,K) + hi/lo split -> bf16 outputs ----
    __nv_bfloat16 *dsth, *dstl;
    int ldd, dcol0;
    bool rope;
    if (isQ)            { dsth = qh; dstl = ql; ldd = 1024; dcol0 = col0; rope = true; }
    else if (col0 < 256){ dsth = kh; dstl = kl; ldd = 256;  dcol0 = col0; rope = true; }
    else                { dsth = vh; dstl = vl; ldd = 256;  dcol0 = col0 - 256; rope = false; }

    const int rbase = row0 + wm * 32 + (lid >> 2);
#pragma unroll
    for (int mi = 0; mi < 2; mi++) {
#pragma unroll
        for (int half = 0; half < 2; half++) {
            const int row = rbase + mi * 16 + half * 8;
            const int pos = row & (LL - 1);
            const int e0 = half * 2;
            if (rope) {
#pragma unroll
                for (int ni = 0; ni < 4; ni++) {
                    const int j0 = ni * 8 + ((lid & 3) << 1);
                    float c0 = ct[pos * 32 + j0],     s0 = st[pos * 32 + j0];
                    float c1 = ct[pos * 32 + j0 + 1], s1 = st[pos * 32 + j0 + 1];
                    float x1a = acc[mi][ni][e0],     x1b = acc[mi][ni][e0 + 1];
                    float x2a = acc[mi][ni + 4][e0], x2b = acc[mi][ni + 4][e0 + 1];
                    float y1a = x1a * c0 - x2a * s0;
                    float y2a = x2a * c0 + x1a * s0;
                    float y1b = x1b * c1 - x2b * s1;
                    float y2b = x2b * c1 + x1b * s1;
                    float h1a = bfhi(y1a), h1b = bfhi(y1b);
                    float h2a = bfhi(y2a), h2b = bfhi(y2b);
                    size_t o1 = (size_t)row * ldd + dcol0 + wn * 64 + j0;
                    size_t o2 = o1 + 32;
                    *(uint32_t*)&dsth[o1] = packbf(h1a, h1b);
                    *(uint32_t*)&dstl[o1] = packbf(y1a - h1a, y1b - h1b);
                    *(uint32_t*)&dsth[o2] = packbf(h2a, h2b);
                    *(uint32_t*)&dstl[o2] = packbf(y2a - h2a, y2b - h2b);
                }
            } else {
#pragma unroll
                for (int ni = 0; ni < 8; ni++) {
                    const int j0 = ni * 8 + ((lid & 3) << 1);
                    float xa = acc[mi][ni][e0], xb = acc[mi][ni][e0 + 1];
                    float ha = bfhi(xa), hb = bfhi(xb);
                    size_t o1 = (size_t)row * ldd + dcol0 + wn * 64 + j0;
                    *(uint32_t*)&dsth[o1] = packbf(ha, hb);
                    *(uint32_t*)&dstl[o1] = packbf(xa - ha, xb - hb);
                }
            }
        }
    }
}

// ---------------------------------------------------------------------------
// Plain tensor-core GEMM for the output projection (fp32 epilogue).
// ---------------------------------------------------------------------------
__global__ __launch_bounds__(256, 2)
void gemm_o(const __nv_bfloat16* __restrict__ Ahi,
            const __nv_bfloat16* __restrict__ Alo,
            const __nv_bfloat16* __restrict__ Bhi,
            const __nv_bfloat16* __restrict__ Blo,
            float* __restrict__ C, int K, int ldc) {
    extern __shared__ char sm[];
    const uint32_t smb = smem_u32(sm);

    const int tid = threadIdx.x;
    const int lid = tid & 31;
    const int wid = tid >> 5;
    const int wm  = wid >> 1;
    const int wn  = wid & 1;
    const int row0 = blockIdx.y << 7;
    const int col0 = blockIdx.x << 7;
    const int NCH = K >> 5;

    const __nv_bfloat16* srcbase[4] = {Ahi, Alo, Bhi, Blo};

    auto prefetch = [&](int c, int stage) {
#pragma unroll
        for (int it = 0; it < 8; it++) {
            int i = tid + (it << 8);
            int s = i >> 9;
            int j = i & 511;
            int r = j >> 2;
            int u = j & 3;
            int grow = (s < 2 ? row0 : col0) + r;
            const __nv_bfloat16* src =
                srcbase[s] + (size_t)grow * K + (c << 5) + (u << 3);
            uint32_t dst = smb + stage * STG_BYTES + s * SUB_BYTES
                         + r * 80 + (u << 4);
            cp16(dst, src);
        }
    };

    prefetch(0, 0); CP_COMMIT();
    prefetch(1, 1); CP_COMMIT();

    float acc[2][8][4];
#pragma unroll
    for (int a = 0; a < 2; a++)
#pragma unroll
        for (int b = 0; b < 8; b++)
#pragma unroll
            for (int d = 0; d < 4; d++) acc[a][b][d] = 0.0f;

    const uint32_t aoff = (uint32_t)((wm * 32 + (lid & 15)) * 80
                                     + ((lid >> 4) << 4));
    const uint32_t boff = (uint32_t)((wn * 64 + ((lid >> 4) << 3) + (lid & 7)) * 80
                                     + (((lid >> 3) & 1) << 4));

    for (int c = 0; c < NCH; c++) {
        CP_WAIT1();
        __syncthreads();

        const uint32_t sb = smb + (c & 1) * STG_BYTES;
        const uint32_t sa_h = sb;
        const uint32_t sa_l = sb + SUB_BYTES;
        const uint32_t sb_h = sb + 2 * SUB_BYTES;
        const uint32_t sb_l = sb + 3 * SUB_BYTES;

#pragma unroll
        for (int ks = 0; ks < 2; ks++) {
            uint32_t Ah[2][4], Al[2][4];
            ldsm4(sa_h + aoff + ks * 32, Ah[0]);
            ldsm4(sa_h + aoff + 16 * 80 + ks * 32, Ah[1]);
            ldsm4(sa_l + aoff + ks * 32, Al[0]);
            ldsm4(sa_l + aoff + 16 * 80 + ks * 32, Al[1]);
#pragma unroll
            for (int g = 0; g < 4; g++) {
                uint32_t Bh[4], Bl[4];
                ldsm4(sb_h + boff + g * (16 * 80) + ks * 32, Bh);
                ldsm4(sb_l + boff + g * (16 * 80) + ks * 32, Bl);
#pragma unroll
                for (int mi = 0; mi < 2; mi++) {
                    mma16816(acc[mi][2 * g],     Ah[mi], Bh);
                    mma16816(acc[mi][2 * g],     Ah[mi], Bl);
                    mma16816(acc[mi][2 * g],     Al[mi], Bh);
                    mma16816(acc[mi][2 * g + 1], Ah[mi], Bh + 2);
                    mma16816(acc[mi][2 * g + 1], Ah[mi], Bl + 2);
                    mma16816(acc[mi][2 * g + 1], Al[mi], Bh + 2);
                }
            }
        }
        __syncthreads();
        if (c + 2 < NCH) prefetch(c + 2, c & 1);
        CP_COMMIT();
    }

#pragma unroll
    for (int mi = 0; mi < 2; mi++) {
        int r0 = row0 + wm * 32 + mi * 16 + (lid >> 2);
#pragma unroll
        for (int ni = 0; ni < 8; ni++) {
            int cc = col0 + wn * 64 + ni * 8 + ((lid & 3) << 1);
            float2 v0; v0.x = acc[mi][ni][0]; v0.y = acc[mi][ni][1];
            float2 v1; v1.x = acc[mi][ni][2]; v1.y = acc[mi][ni][3];
            *(float2*)(C + (size_t)r0 * ldc + cc)       = v0;
            *(float2*)(C + (size_t)(r0 + 8) * ldc + cc) = v1;
        }
    }
}

// ---------------------------------------------------------------------------
// Tensor-core flash attention, analytic-max softmax, 2-stage KV pipeline
// (round-10 scheme). Per-tile body split into two 32-key HALVES so S and
// PA live ranges halve (64->32 regs each): peak live set ~230 < 255 cap,
// eliminating register spills. ldsm/MMA counts and sharing identical.
// ---------------------------------------------------------------------------
#define AST 144
#define KVSUB (64 * AST)
#define KVSTG (4 * KVSUB)          // 36864
#define QSUB  KVSTG
#define ATT_SMEM (2 * KVSTG)       // 73728

__global__ __launch_bounds__(256, 1)
void attn_mma(const __nv_bfloat16* __restrict__ qh, const __nv_bfloat16* __restrict__ ql,
              const __nv_bfloat16* __restrict__ kh, const __nv_bfloat16* __restrict__ kl,
              const __nv_bfloat16* __restrict__ vh, const __nv_bfloat16* __restrict__ vl,
              __nv_bfloat16* __restrict__ cthi, __nv_bfloat16* __restrict__ ctlo) {
    extern __shared__ char sm[];
    const uint32_t smb = smem_u32(sm);

    const int tid = threadIdx.x;
    const int lid = tid & 31;
    const int wid = tid >> 5;
    const int q0  = blockIdx.x << 8;
    const int h   = blockIdx.y;
    const int b   = blockIdx.z;
    const int kvh2 = h >> 2;

    const float slope = exp2f(-0.5f * (float)(h + 1));
    const float scale = 0.125f;

    // ---- stage Q (hi @ 0, lo @ QSUB) through the KV buffers ----
#pragma unroll
    for (int t = 0; t < 16; t++) {
        int i = tid + (t << 8);
        int s = i >> 11;
        int j = i & 2047;
        int r = j >> 3;
        int u = j & 7;
        const __nv_bfloat16* src =
            (s ? ql : qh) + (size_t)(b * LL + q0 + r) * 1024 + h * 64 + (u << 3);
        cp16(smb + s * QSUB + r * AST + (u << 4), src);
    }
    CP_COMMIT();
    CP_WAIT0();
    __syncthreads();

    // ---- Q fragments for both 16-row blocks -> registers ----
    uint32_t AQh[2][4][4], AQl[2][4][4];
#pragma unroll
    for (int bl = 0; bl < 2; bl++) {
        uint32_t qaddr = (uint32_t)((wid * 32 + bl * 16 + (lid & 15)) * AST
                                    + ((lid >> 4) << 4));
#pragma unroll
        for (int kt = 0; kt < 4; kt++) {
            ldsm4(smb + qaddr + kt * 32, AQh[bl][kt]);
            ldsm4(smb + QSUB + qaddr + kt * 32, AQl[bl][kt]);
        }
    }
    __syncthreads();   // all warps done reading Q before KV overwrites

    // ---- KV pipeline (2 stages) ----
    const __nv_bfloat16* kvsrc[4] = {kh, kl, vh, vl};
    auto pf = [&](int c, int st) {
#pragma unroll
        for (int t = 0; t < 8; t++) {
            int i = tid + (t << 8);
            int s = i >> 9;
            int j = i & 511;
            int r = j >> 3;
            int u = j & 7;
            const __nv_bfloat16* src =
                kvsrc[s] + (size_t)(b * LL + (c << 6) + r) * 256 + kvh2 * 64 + (u << 3);
            cp16(smb + st * KVSTG + s * KVSUB + r * AST + (u << 4), src);
        }
    };
    pf(0, 0); CP_COMMIT();
    pf(1, 1); CP_COMMIT();

    const uint32_t kaddr = (uint32_t)((((lid >> 4) << 3) + (lid & 7)) * AST
                                      + (((lid >> 3) & 1) << 4));
    const uint32_t vaddr = (uint32_t)((lid & 15) * AST + ((lid >> 4) << 4));

    float o[2][8][4];
    float lsum[2][2];
#pragma unroll
    for (int bl = 0; bl < 2; bl++) {
#pragma unroll
        for (int i = 0; i < 8; i++)
#pragma unroll
            for (int e = 0; e < 4; e++) o[bl][i][e] = 0.0f;
        lsum[bl][0] = 0.0f; lsum[bl][1] = 0.0f;
    }

    const int NTILES = LL / 64;

    for (int c = 0; c < NTILES; c++) {
        CP_WAIT1();
        __syncthreads();

        const uint32_t sb  = smb + (c & 1) * KVSTG;
        const uint32_t skh = sb;
        const uint32_t skl = sb + KVSUB;
        const uint32_t svh = sb + 2 * KVSUB;
        const uint32_t svl = sb + 3 * KVSUB;

        const float bias00 =
            slope * ((float)((c << 6) + 2 * (lid & 3)) - 2047.0f) - 8.0f;

        // ==== two 32-key halves: QK -> softmax -> PV per half ====
#pragma unroll
        for (int half = 0; half < 2; half++) {
            // ---- S = Q.K^T for this half (keys half*32 .. half*32+31) ----
            float S[2][4][4];
#pragma unroll
            for (int bl = 0; bl < 2; bl++)
#pragma unroll
                for (int i = 0; i < 4; i++)
#pragma unroll
                    for (int e = 0; e < 4; e++) S[bl][i][e] = 0.0f;

#pragma unroll
            for (int g2 = 0; g2 < 2; g2++) {
                const int g = half * 2 + g2;
#pragma unroll
                for (int ks = 0; ks < 4; ks++) {
                    uint32_t Bh[4], Bl[4];
                    uint32_t base = (g << 4) * AST + kaddr + (ks << 5);
                    ldsm4(skh + base, Bh);
                    ldsm4(skl + base, Bl);
#pragma unroll
                    for (int bl = 0; bl < 2; bl++) {
                        mma16816(S[bl][2 * g2],     AQh[bl][ks], Bh);
                        mma16816(S[bl][2 * g2],     AQh[bl][ks], Bl);
                        mma16816(S[bl][2 * g2],     AQl[bl][ks], Bh);
                        mma16816(S[bl][2 * g2 + 1], AQh[bl][ks], Bh + 2);
                        mma16816(S[bl][2 * g2 + 1], AQh[bl][ks], Bl + 2);
                        mma16816(S[bl][2 * g2 + 1], AQl[bl][ks], Bh + 2);
                    }
                }
            }

            // ---- softmax (analytic max) + P -> A-fragments ----
            uint32_t PAh[2][2][4], PAl[2][2][4];
            const float biasH = bias00 + slope * (float)(half << 5);
#pragma unroll
            for (int bl = 0; bl < 2; bl++) {
#pragma unroll
                for (int nt = 0; nt < 4; nt++) {
                    const float be = biasH + slope * (float)(nt << 3);
                    const float bo = be + slope;
                    float p0 = __expf(fmaf(S[bl][nt][0], scale, be));
                    float p1 = __expf(fmaf(S[bl][nt][1], scale, bo));
                    float p2 = __expf(fmaf(S[bl][nt][2], scale, be));
                    float p3 = __expf(fmaf(S[bl][nt][3], scale, bo));
                    lsum[bl][0] += p0 + p1;
                    lsum[bl][1] += p2 + p3;
                    S[bl][nt][0] = p0; S[bl][nt][1] = p1;
                    S[bl][nt][2] = p2; S[bl][nt][3] = p3;
                }
#pragma unroll
                for (int kt2 = 0; kt2 < 2; kt2++) {
                    float p00 = S[bl][2 * kt2][0],     p01 = S[bl][2 * kt2][1];
                    float p02 = S[bl][2 * kt2][2],     p03 = S[bl][2 * kt2][3];
                    float p10 = S[bl][2 * kt2 + 1][0], p11 = S[bl][2 * kt2 + 1][1];
                    float p12 = S[bl][2 * kt2 + 1][2], p13 = S[bl][2 * kt2 + 1][3];
                    float h00 = bfhi(p00), h01 = bfhi(p01);
                    float h02 = bfhi(p02), h03 = bfhi(p03);
                    float h10 = bfhi(p10), h11 = bfhi(p11);
                    float h12 = bfhi(p12), h13 = bfhi(p13);
                    PAh[bl][kt2][0] = packbf(h00, h01);
                    PAh[bl][kt2][1] = packbf(h02, h03);
                    PAh[bl][kt2][2] = packbf(h10, h11);
                    PAh[bl][kt2][3] = packbf(h12, h13);
                    PAl[bl][kt2][0] = packbf(p00 - h00, p01 - h01);
                    PAl[bl][kt2][1] = packbf(p02 - h02, p03 - h03);
                    PAl[bl][kt2][2] = packbf(p10 - h10, p11 - h11);
                    PAl[bl][kt2][3] = packbf(p12 - h12, p13 - h13);
                }
            }

            // ---- O += P @ V for this half's 32 keys ----
#pragma unroll
            for (int dg = 0; dg < 4; dg++) {
#pragma unroll
                for (int kt2 = 0; kt2 < 2; kt2++) {
                    const int kt = half * 2 + kt2;
                    uint32_t Bvh[4], Bvl[4];
                    uint32_t base = (kt << 4) * AST + vaddr + (dg << 5);
                    ldsm4t(svh + base, Bvh);
                    ldsm4t(svl + base, Bvl);
#pragma unroll
                    for (int bl = 0; bl < 2; bl++) {
                        mma16816(o[bl][2 * dg],     PAh[bl][kt2], Bvh);
                        mma16816(o[bl][2 * dg],     PAh[bl][kt2], Bvl);
                        mma16816(o[bl][2 * dg],     PAl[bl][kt2], Bvh);
                        mma16816(o[bl][2 * dg + 1], PAh[bl][kt2], Bvh + 2);
                        mma16816(o[bl][2 * dg + 1], PAh[bl][kt2], Bvl + 2);
                        mma16816(o[bl][2 * dg + 1], PAl[bl][kt2], Bvh + 2);
                    }
                }
            }
        }

        __syncthreads();
        if (c + 2 < NTILES) pf(c + 2, c & 1);
        CP_COMMIT();
    }

    // ---- epilogue: reduce lsum across quad lanes, normalize, split ----
#pragma unroll
    for (int bl = 0; bl < 2; bl++) {
#pragma unroll
        for (int r = 0; r < 2; r++) {
            lsum[bl][r] += __shfl_xor_sync(0xffffffffu, lsum[bl][r], 1);
            lsum[bl][r] += __shfl_xor_sync(0xffffffffu, lsum[bl][r], 2);
        }
        float inv0 = 1.0f / lsum[bl][0];
        float inv1 = 1.0f / lsum[bl][1];
        const int r0 = b * LL + q0 + wid * 32 + bl * 16 + (lid >> 2);
#pragma unroll
        for (int nt = 0; nt < 8; nt++) {
            int cc = h * 64 + nt * 8 + ((lid & 3) << 1);
            float v0 = o[bl][nt][0] * inv0, v1 = o[bl][nt][1] * inv0;
            float v2 = o[bl][nt][2] * inv1, v3 = o[bl][nt][3] * inv1;
            float h0 = bfhi(v0), h1 = bfhi(v1), h2 = bfhi(v2), h3 = bfhi(v3);
            size_t oa = (size_t)r0 * 1024 + cc;
            size_t ob = (size_t)(r0 + 8) * 1024 + cc;
            *(uint32_t*)&cthi[oa] = packbf(h0, h1);
            *(uint32_t*)&ctlo[oa] = packbf(v0 - h0, v1 - h1);
            *(uint32_t*)&cthi[ob] = packbf(h2, h3);
            *(uint32_t*)&ctlo[ob] = packbf(v2 - h2, v3 - h3);
        }
    }
}

// ---------------------------------------------------------------------------
// kernel_launch: 0 prep_x  1 prep_w  2 gemm_qkv  3 attn_mma(capture)  4 gemm_o
// ---------------------------------------------------------------------------
extern "C" void kernel_launch(void* const* d_in, const int* in_sizes, int n_in,
                              void* d_out, int out_size) {
    const float* x  = (const float*)d_in[0];
    const float* Wq = (const float*)d_in[1];
    const float* Wk = (const float*)d_in[2];
    const float* Wv = (const float*)d_in[3];
    const float* Wo = (const float*)d_in[4];
    float* out = (float*)d_out;

    __nv_bfloat16 *xhi, *xlo, *cthi, *ctlo;
    __nv_bfloat16 *wqh, *wql, *wkvh, *wkvl, *woh, *wol;
    __nv_bfloat16 *aqh, *aql, *akh, *akl, *avh, *avl;
    float *ct, *st;
    cudaGetSymbolAddress((void**)&xhi,  g_xhi);
    cudaGetSymbolAddress((void**)&xlo,  g_xlo);
    cudaGetSymbolAddress((void**)&cthi, g_ctxhi);
    cudaGetSymbolAddress((void**)&ctlo, g_ctxlo);
    cudaGetSymbolAddress((void**)&wqh,  g_wqt_h);
    cudaGetSymbolAddress((void**)&wql,  g_wqt_l);
    cudaGetSymbolAddress((void**)&wkvh, g_wkvt_h);
    cudaGetSymbolAddress((void**)&wkvl, g_wkvt_l);
    cudaGetSymbolAddress((void**)&woh,  g_wot_h);
    cudaGetSymbolAddress((void**)&wol,  g_wot_l);
    cudaGetSymbolAddress((void**)&aqh,  g_qh);
    cudaGetSymbolAddress((void**)&aql,  g_ql);
    cudaGetSymbolAddress((void**)&akh,  g_kh);
    cudaGetSymbolAddress((void**)&akl,  g_kl);
    cudaGetSymbolAddress((void**)&avh,  g_vh);
    cudaGetSymbolAddress((void**)&avl,  g_vl);
    cudaGetSymbolAddress((void**)&ct,   g_cos);
    cudaGetSymbolAddress((void**)&st,   g_sin);

    const int smem_gemm = 2 * STG_BYTES;
    cudaFuncSetAttribute(gemm_qkv, cudaFuncAttributeMaxDynamicSharedMemorySize,
                         smem_gemm);
    cudaFuncSetAttribute(gemm_o, cudaFuncAttributeMaxDynamicSharedMemorySize,
                         smem_gemm);
    cudaFuncSetAttribute(attn_mma, cudaFuncAttributeMaxDynamicSharedMemorySize,
                         ATT_SMEM);

    dim3 blk(256);

    // 0: x split + rope tables
    prep_x<<<4096 + 256, blk>>>(x, xhi, xlo, ct, st);
    // 1: weight transposes+splits
    prep_w<<<2560, blk>>>(Wq, Wk, Wv, Wo, wqh, wql, wkvh, wkvl, woh, wol);

    // 2: QKV projection with fused RoPE + bf16 split epilogue
    gemm_qkv<<<dim3(12, BL / 128), blk, smem_gemm>>>(
        xhi, xlo, wqh, wql, wkvh, wkvl, aqh, aql, akh, akl, avh, avl, ct, st);

    // 3: tensor-core attention (half-split, low-register)  <-- capture slot
    attn_mma<<<dim3(LL / 256, HH, BB), blk, ATT_SMEM>>>(
        aqh, aql, akh, akl, avh, avl, cthi, ctlo);

    // 4: output projection
    gemm_o<<<dim3(8, BL / 128), blk, smem_gemm>>>(
        cthi, ctlo, woh, wol, out, DD, DD);
}

// round 14
// speedup vs baseline: 1.0317x; 1.0019x over previous
#include <cuda_runtime.h>
#include <cuda_bf16.h>
#include <math.h>
#include <stdint.h>

// Problem constants
#define BB   2
#define LL   2048
#define DD   1024
#define HH   16
#define KVH  4
#define HDIM 64
#define BL   (BB * LL)    // 4096

typedef unsigned long long ull;

// ---------------------------------------------------------------------------
// mma.sync / ldmatrix / cp.async helpers (baseline PTX ISA)
// ---------------------------------------------------------------------------
__device__ __forceinline__ uint32_t smem_u32(const void* p) {
    uint32_t a;
    asm("{ .reg .u64 t; cvta.to.shared.u64 t, %1; cvt.u32.u64 %0, t; }"
        : "=r"(a) : "l"(p));
    return a;
}
__device__ __forceinline__ void ldsm4(uint32_t addr, uint32_t* r) {
    asm volatile("ldmatrix.sync.aligned.m8n8.x4.shared.b16 {%0,%1,%2,%3}, [%4];"
                 : "=r"(r[0]), "=r"(r[1]), "=r"(r[2]), "=r"(r[3]) : "r"(addr));
}
__device__ __forceinline__ void ldsm4t(uint32_t addr, uint32_t* r) {
    asm volatile("ldmatrix.sync.aligned.m8n8.x4.trans.shared.b16 {%0,%1,%2,%3}, [%4];"
                 : "=r"(r[0]), "=r"(r[1]), "=r"(r[2]), "=r"(r[3]) : "r"(addr));
}
__device__ __forceinline__ void mma16816(float* d, const uint32_t* a,
                                         const uint32_t* b) {
    asm volatile(
        "mma.sync.aligned.m16n8k16.row.col.f32.bf16.bf16.f32 "
        "{%0,%1,%2,%3}, {%4,%5,%6,%7}, {%8,%9}, {%0,%1,%2,%3};"
        : "+f"(d[0]), "+f"(d[1]), "+f"(d[2]), "+f"(d[3])
        : "r"(a[0]), "r"(a[1]), "r"(a[2]), "r"(a[3]), "r"(b[0]), "r"(b[1]));
}
__device__ __forceinline__ void cp16(uint32_t dst, const void* src) {
    asm volatile("cp.async.cg.shared.global [%0], [%1], 16;"
                 :: "r"(dst), "l"(src) : "memory");
}
#define CP_COMMIT() asm volatile("cp.async.commit_group;" ::: "memory")
#define CP_WAIT2()  asm volatile("cp.async.wait_group 2;" ::: "memory")
#define CP_WAIT1()  asm volatile("cp.async.wait_group 1;" ::: "memory")
#define CP_WAIT0()  asm volatile("cp.async.wait_group 0;" ::: "memory")

__device__ __forceinline__ uint32_t packbf(float lo, float hi) {
    __nv_bfloat162 t = __floats2bfloat162_rn(lo, hi);
    return *(uint32_t*)&t;
}
__device__ __forceinline__ float bfhi(float v) {
    return __bfloat162float(__float2bfloat16(v));
}

// ---------------------------------------------------------------------------
// Scratch (__device__ globals — no allocations allowed)
// ---------------------------------------------------------------------------
__device__ __nv_bfloat16 g_xhi[BL * DD];
__device__ __nv_bfloat16 g_xlo[BL * DD];
__device__ __nv_bfloat16 g_ctxhi[BL * DD];
__device__ __nv_bfloat16 g_ctxlo[BL * DD];
__device__ __nv_bfloat16 g_wqt_h[DD * DD];
__device__ __nv_bfloat16 g_wqt_l[DD * DD];
__device__ __nv_bfloat16 g_wkvt_h[512 * DD];
__device__ __nv_bfloat16 g_wkvt_l[512 * DD];
__device__ __nv_bfloat16 g_wot_h[DD * DD];
__device__ __nv_bfloat16 g_wot_l[DD * DD];

__device__ __nv_bfloat16 g_qh[BL * DD];
__device__ __nv_bfloat16 g_ql[BL * DD];
__device__ __nv_bfloat16 g_kh[BL * 256];
__device__ __nv_bfloat16 g_kl[BL * 256];
__device__ __nv_bfloat16 g_vh[BL * 256];
__device__ __nv_bfloat16 g_vl[BL * 256];

__device__ float g_cos[LL * 32];
__device__ float g_sin[LL * 32];

// ---------------------------------------------------------------------------
// prep_x: x split (4096 blocks) + rope tables (256 blocks)
// ---------------------------------------------------------------------------
__global__ __launch_bounds__(256)
void prep_x(const float* __restrict__ x,
            __nv_bfloat16* __restrict__ xhi, __nv_bfloat16* __restrict__ xlo,
            float* __restrict__ ct, float* __restrict__ st) {
    const int bid = blockIdx.x;
    if (bid < 4096) {
        int i = bid * 256 + threadIdx.x;
        float4 v = ((const float4*)x)[i];
        float vv[4] = {v.x, v.y, v.z, v.w};
        __nv_bfloat16 h[4], l[4];
#pragma unroll
        for (int j = 0; j < 4; j++) {
            h[j] = __float2bfloat16(vv[j]);
            l[j] = __float2bfloat16(vv[j] - __bfloat162float(h[j]));
        }
        ((uint64_t*)xhi)[i] = *(uint64_t*)h;
        ((uint64_t*)xlo)[i] = *(uint64_t*)l;
    } else {
        int i = (bid - 4096) * 256 + threadIdx.x;
        int pos = i >> 5, j = i & 31;
        float inv = powf(10000.0f, -(float)j * (1.0f / 32.0f));
        float s, c;
        sincosf((float)pos * inv, &s, &c);
        ct[i] = c;
        st[i] = s;
    }
}

// ---------------------------------------------------------------------------
// prep_w: weight transposes+splits
// ---------------------------------------------------------------------------
__global__ __launch_bounds__(256)
void prep_w(const float* __restrict__ Wq, const float* __restrict__ Wk,
            const float* __restrict__ Wv, const float* __restrict__ Wo,
            __nv_bfloat16* __restrict__ wqh, __nv_bfloat16* __restrict__ wql,
            __nv_bfloat16* __restrict__ wkvh, __nv_bfloat16* __restrict__ wkvl,
            __nv_bfloat16* __restrict__ woh, __nv_bfloat16* __restrict__ wol) {
    __shared__ float t[32][33];
    int j = blockIdx.x;
    const float* W;
    __nv_bfloat16 *hiT, *loT;
    int Nd, rowoff = 0, bx, by;
    if (j < 1024) { W = Wq; hiT = wqh; loT = wql; Nd = 1024;
                    bx = j & 31; by = j >> 5; }
    else if (j < 1536) {
        int j2 = j - 1024;
        int z = j2 >> 8;
        int r = j2 & 255;
        bx = r & 7; by = r >> 3;
        Nd = 256;
        hiT = wkvh; loT = wkvl;
        if (z == 0) { W = Wk; }
        else        { W = Wv; rowoff = 256; }
    } else {
        int j2 = j - 1536;
        W = Wo; hiT = woh; loT = wol; Nd = 1024;
        bx = j2 & 31; by = j2 >> 5;
    }
    int n0 = bx << 5, k0 = by << 5;
    int tx = threadIdx.x & 31, ty = threadIdx.x >> 5;
    for (int r = ty; r < 32; r += 8)
        t[r][tx] = W[(size_t)(k0 + r) * Nd + n0 + tx];
    __syncthreads();
    for (int r = ty; r < 32; r += 8) {
        float v = t[tx][r];
        __nv_bfloat16 h = __float2bfloat16(v);
        size_t o = (size_t)(rowoff + n0 + r) * DD + k0 + tx;
        hiT[o] = h;
        loT[o] = __float2bfloat16(v - __bfloat162float(h));
    }
}

// ---------------------------------------------------------------------------
// QKV GEMM (mma.sync bf16x3) with fused RoPE + bf16 hi/lo split epilogue.
// ---------------------------------------------------------------------------
#define STG_BYTES 40960
#define SUB_BYTES 10240

__global__ __launch_bounds__(256, 2)
void gemm_qkv(const __nv_bfloat16* __restrict__ Ahi,
              const __nv_bfloat16* __restrict__ Alo,
              const __nv_bfloat16* __restrict__ Wqh,
              const __nv_bfloat16* __restrict__ Wql,
              const __nv_bfloat16* __restrict__ Wkvh,
              const __nv_bfloat16* __restrict__ Wkvl,
              __nv_bfloat16* __restrict__ qh, __nv_bfloat16* __restrict__ ql,
              __nv_bfloat16* __restrict__ kh, __nv_bfloat16* __restrict__ kl,
              __nv_bfloat16* __restrict__ vh, __nv_bfloat16* __restrict__ vl,
              const float* __restrict__ ct, const float* __restrict__ st) {
    extern __shared__ char sm[];
    const uint32_t smb = smem_u32(sm);
    const int K = DD;

    const int tid = threadIdx.x;
    const int lid = tid & 31;
    const int wid = tid >> 5;
    const int wm  = wid >> 1;
    const int wn  = wid & 1;
    const int row0 = blockIdx.y << 7;
    const int NCH = K >> 5;

    const bool isQ = (int)blockIdx.x < 8;
    const int col0 = isQ ? (blockIdx.x << 7) : (((int)blockIdx.x - 8) << 7);
    const __nv_bfloat16* Bhi = isQ ? Wqh : Wkvh;
    const __nv_bfloat16* Blo = isQ ? Wql : Wkvl;

    const __nv_bfloat16* srcbase[4] = {Ahi, Alo, Bhi, Blo};

    auto prefetch = [&](int c, int stage) {
#pragma unroll
        for (int it = 0; it < 8; it++) {
            int i = tid + (it << 8);
            int s = i >> 9;
            int j = i & 511;
            int r = j >> 2;
            int u = j & 3;
            int grow = (s < 2 ? row0 : col0) + r;
            const __nv_bfloat16* src =
                srcbase[s] + (size_t)grow * K + (c << 5) + (u << 3);
            uint32_t dst = smb + stage * STG_BYTES + s * SUB_BYTES
                         + r * 80 + (u << 4);
            cp16(dst, src);
        }
    };

    prefetch(0, 0); CP_COMMIT();
    prefetch(1, 1); CP_COMMIT();

    float acc[2][8][4];
#pragma unroll
    for (int a = 0; a < 2; a++)
#pragma unroll
        for (int b = 0; b < 8; b++)
#pragma unroll
            for (int d = 0; d < 4; d++) acc[a][b][d] = 0.0f;

    const uint32_t aoff = (uint32_t)((wm * 32 + (lid & 15)) * 80
                                     + ((lid >> 4) << 4));
    const uint32_t boff = (uint32_t)((wn * 64 + ((lid >> 4) << 3) + (lid & 7)) * 80
                                     + (((lid >> 3) & 1) << 4));

    for (int c = 0; c < NCH; c++) {
        CP_WAIT1();
        __syncthreads();

        const uint32_t sb = smb + (c & 1) * STG_BYTES;
        const uint32_t sa_h = sb;
        const uint32_t sa_l = sb + SUB_BYTES;
        const uint32_t sb_h = sb + 2 * SUB_BYTES;
        const uint32_t sb_l = sb + 3 * SUB_BYTES;

#pragma unroll
        for (int ks = 0; ks < 2; ks++) {
            uint32_t Ah[2][4], Al[2][4];
            ldsm4(sa_h + aoff + ks * 32, Ah[0]);
            ldsm4(sa_h + aoff + 16 * 80 + ks * 32, Ah[1]);
            ldsm4(sa_l + aoff + ks * 32, Al[0]);
            ldsm4(sa_l + aoff + 16 * 80 + ks * 32, Al[1]);
#pragma unroll
            for (int g = 0; g < 4; g++) {
                uint32_t Bh[4], Bl[4];
                ldsm4(sb_h + boff + g * (16 * 80) + ks * 32, Bh);
                ldsm4(sb_l + boff + g * (16 * 80) + ks * 32, Bl);
#pragma unroll
                for (int mi = 0; mi < 2; mi++) {
                    mma16816(acc[mi][2 * g],     Ah[mi], Bh);
                    mma16816(acc[mi][2 * g],     Ah[mi], Bl);
                    mma16816(acc[mi][2 * g],     Al[mi], Bh);
                    mma16816(acc[mi][2 * g + 1], Ah[mi], Bh + 2);
                    mma16816(acc[mi][2 * g + 1], Ah[mi], Bl + 2);
                    mma16816(acc[mi][2 * g + 1], Al[mi], Bh + 2);
                }
            }
        }
        __syncthreads();
        if (c + 2 < NCH) prefetch(c + 2, c & 1);
        CP_COMMIT();
    }

    // ---- fused epilogue: RoPE (Q,K) + hi/lo split -> bf16 outputs ----
    __nv_bfloat16 *dsth, *dstl;
    int ldd, dcol0;
    bool rope;
    if (isQ)            { dsth = qh; dstl = ql; ldd = 1024; dcol0 = col0; rope = true; }
    else if (col0 < 256){ dsth = kh; dstl = kl; ldd = 256;  dcol0 = col0; rope = true; }
    else                { dsth = vh; dstl = vl; ldd = 256;  dcol0 = col0 - 256; rope = false; }

    const int rbase = row0 + wm * 32 + (lid >> 2);
#pragma unroll
    for (int mi = 0; mi < 2; mi++) {
#pragma unroll
        for (int half = 0; half < 2; half++) {
            const int row = rbase + mi * 16 + half * 8;
            const int pos = row & (LL - 1);
            const int e0 = half * 2;
            if (rope) {
#pragma unroll
                for (int ni = 0; ni < 4; ni++) {
                    const int j0 = ni * 8 + ((lid & 3) << 1);
                    float c0 = ct[pos * 32 + j0],     s0 = st[pos * 32 + j0];
                    float c1 = ct[pos * 32 + j0 + 1], s1 = st[pos * 32 + j0 + 1];
                    float x1a = acc[mi][ni][e0],     x1b = acc[mi][ni][e0 + 1];
                    float x2a = acc[mi][ni + 4][e0], x2b = acc[mi][ni + 4][e0 + 1];
                    float y1a = x1a * c0 - x2a * s0;
                    float y2a = x2a * c0 + x1a * s0;
                    float y1b = x1b * c1 - x2b * s1;
                    float y2b = x2b * c1 + x1b * s1;
                    float h1a = bfhi(y1a), h1b = bfhi(y1b);
                    float h2a = bfhi(y2a), h2b = bfhi(y2b);
                    size_t o1 = (size_t)row * ldd + dcol0 + wn * 64 + j0;
                    size_t o2 = o1 + 32;
                    *(uint32_t*)&dsth[o1] = packbf(h1a, h1b);
                    *(uint32_t*)&dstl[o1] = packbf(y1a - h1a, y1b - h1b);
                    *(uint32_t*)&dsth[o2] = packbf(h2a, h2b);
                    *(uint32_t*)&dstl[o2] = packbf(y2a - h2a, y2b - h2b);
                }
            } else {
#pragma unroll
                for (int ni = 0; ni < 8; ni++) {
                    const int j0 = ni * 8 + ((lid & 3) << 1);
                    float xa = acc[mi][ni][e0], xb = acc[mi][ni][e0 + 1];
                    float ha = bfhi(xa), hb = bfhi(xb);
                    size_t o1 = (size_t)row * ldd + dcol0 + wn * 64 + j0;
                    *(uint32_t*)&dsth[o1] = packbf(ha, hb);
                    *(uint32_t*)&dstl[o1] = packbf(xa - ha, xb - hb);
                }
            }
        }
    }
}

// ---------------------------------------------------------------------------
// Plain tensor-core GEMM for the output projection (fp32 epilogue).
// ---------------------------------------------------------------------------
__global__ __launch_bounds__(256, 2)
void gemm_o(const __nv_bfloat16* __restrict__ Ahi,
            const __nv_bfloat16* __restrict__ Alo,
            const __nv_bfloat16* __restrict__ Bhi,
            const __nv_bfloat16* __restrict__ Blo,
            float* __restrict__ C, int K, int ldc) {
    extern __shared__ char sm[];
    const uint32_t smb = smem_u32(sm);

    const int tid = threadIdx.x;
    const int lid = tid & 31;
    const int wid = tid >> 5;
    const int wm  = wid >> 1;
    const int wn  = wid & 1;
    const int row0 = blockIdx.y << 7;
    const int col0 = blockIdx.x << 7;
    const int NCH = K >> 5;

    const __nv_bfloat16* srcbase[4] = {Ahi, Alo, Bhi, Blo};

    auto prefetch = [&](int c, int stage) {
#pragma unroll
        for (int it = 0; it < 8; it++) {
            int i = tid + (it << 8);
            int s = i >> 9;
            int j = i & 511;
            int r = j >> 2;
            int u = j & 3;
            int grow = (s < 2 ? row0 : col0) + r;
            const __nv_bfloat16* src =
                srcbase[s] + (size_t)grow * K + (c << 5) + (u << 3);
            uint32_t dst = smb + stage * STG_BYTES + s * SUB_BYTES
                         + r * 80 + (u << 4);
            cp16(dst, src);
        }
    };

    prefetch(0, 0); CP_COMMIT();
    prefetch(1, 1); CP_COMMIT();

    float acc[2][8][4];
#pragma unroll
    for (int a = 0; a < 2; a++)
#pragma unroll
        for (int b = 0; b < 8; b++)
#pragma unroll
            for (int d = 0; d < 4; d++) acc[a][b][d] = 0.0f;

    const uint32_t aoff = (uint32_t)((wm * 32 + (lid & 15)) * 80
                                     + ((lid >> 4) << 4));
    const uint32_t boff = (uint32_t)((wn * 64 + ((lid >> 4) << 3) + (lid & 7)) * 80
                                     + (((lid >> 3) & 1) << 4));

    for (int c = 0; c < NCH; c++) {
        CP_WAIT1();
        __syncthreads();

        const uint32_t sb = smb + (c & 1) * STG_BYTES;
        const uint32_t sa_h = sb;
        const uint32_t sa_l = sb + SUB_BYTES;
        const uint32_t sb_h = sb + 2 * SUB_BYTES;
        const uint32_t sb_l = sb + 3 * SUB_BYTES;

#pragma unroll
        for (int ks = 0; ks < 2; ks++) {
            uint32_t Ah[2][4], Al[2][4];
            ldsm4(sa_h + aoff + ks * 32, Ah[0]);
            ldsm4(sa_h + aoff + 16 * 80 + ks * 32, Ah[1]);
            ldsm4(sa_l + aoff + ks * 32, Al[0]);
            ldsm4(sa_l + aoff + 16 * 80 + ks * 32, Al[1]);
#pragma unroll
            for (int g = 0; g < 4; g++) {
                uint32_t Bh[4], Bl[4];
                ldsm4(sb_h + boff + g * (16 * 80) + ks * 32, Bh);
                ldsm4(sb_l + boff + g * (16 * 80) + ks * 32, Bl);
#pragma unroll
                for (int mi = 0; mi < 2; mi++) {
                    mma16816(acc[mi][2 * g],     Ah[mi], Bh);
                    mma16816(acc[mi][2 * g],     Ah[mi], Bl);
                    mma16816(acc[mi][2 * g],     Al[mi], Bh);
                    mma16816(acc[mi][2 * g + 1], Ah[mi], Bh + 2);
                    mma16816(acc[mi][2 * g + 1], Ah[mi], Bl + 2);
                    mma16816(acc[mi][2 * g + 1], Al[mi], Bh + 2);
                }
            }
        }
        __syncthreads();
        if (c + 2 < NCH) prefetch(c + 2, c & 1);
        CP_COMMIT();
    }

#pragma unroll
    for (int mi = 0; mi < 2; mi++) {
        int r0 = row0 + wm * 32 + mi * 16 + (lid >> 2);
#pragma unroll
        for (int ni = 0; ni < 8; ni++) {
            int cc = col0 + wn * 64 + ni * 8 + ((lid & 3) << 1);
            float2 v0; v0.x = acc[mi][ni][0]; v0.y = acc[mi][ni][1];
            float2 v1; v1.x = acc[mi][ni][2]; v1.y = acc[mi][ni][3];
            *(float2*)(C + (size_t)r0 * ldc + cc)       = v0;
            *(float2*)(C + (size_t)(r0 + 8) * ldc + cc) = v1;
        }
    }
}

// ---------------------------------------------------------------------------
// Tensor-core flash attention, analytic-max softmax, half-split tiles.
// Q lives PERMANENTLY in smem (hi+lo); only AQh persists in registers.
// AQl fragments are re-ldsm'd per (half, ks) from the resident Q-lo region,
// cutting 64 persistent registers and eliminating spills.
// smem: Qhi(36864) + Qlo(36864) + 2 KV stages(73728) = 147456.
// ---------------------------------------------------------------------------
#define AST 144
#define KVSUB (64 * AST)
#define KVSTG (4 * KVSUB)          // 36864
#define QSUB  KVSTG
#define KV_OFF (2 * QSUB)          // 73728
#define ATT_SMEM (KV_OFF + 2 * KVSTG)   // 147456

__global__ __launch_bounds__(256, 1)
void attn_mma(const __nv_bfloat16* __restrict__ qh, const __nv_bfloat16* __restrict__ ql,
              const __nv_bfloat16* __restrict__ kh, const __nv_bfloat16* __restrict__ kl,
              const __nv_bfloat16* __restrict__ vh, const __nv_bfloat16* __restrict__ vl,
              __nv_bfloat16* __restrict__ cthi, __nv_bfloat16* __restrict__ ctlo) {
    extern __shared__ char sm[];
    const uint32_t smb = smem_u32(sm);

    const int tid = threadIdx.x;
    const int lid = tid & 31;
    const int wid = tid >> 5;
    const int q0  = blockIdx.x << 8;
    const int h   = blockIdx.y;
    const int b   = blockIdx.z;
    const int kvh2 = h >> 2;

    const float slope = exp2f(-0.5f * (float)(h + 1));
    const float scale = 0.125f;

    // ---- stage Q into its PERMANENT smem region (hi @0, lo @QSUB) ----
#pragma unroll
    for (int t = 0; t < 16; t++) {
        int i = tid + (t << 8);
        int s = i >> 11;
        int j = i & 2047;
        int r = j >> 3;
        int u = j & 7;
        const __nv_bfloat16* src =
            (s ? ql : qh) + (size_t)(b * LL + q0 + r) * 1024 + h * 64 + (u << 3);
        cp16(smb + s * QSUB + r * AST + (u << 4), src);
    }
    CP_COMMIT();

    // ---- KV pipeline (2 stages) starts immediately, overlapping Q ----
    const __nv_bfloat16* kvsrc[4] = {kh, kl, vh, vl};
    auto pf = [&](int c, int st) {
#pragma unroll
        for (int t = 0; t < 8; t++) {
            int i = tid + (t << 8);
            int s = i >> 9;
            int j = i & 511;
            int r = j >> 3;
            int u = j & 7;
            const __nv_bfloat16* src =
                kvsrc[s] + (size_t)(b * LL + (c << 6) + r) * 256 + kvh2 * 64 + (u << 3);
            cp16(smb + KV_OFF + st * KVSTG + s * KVSUB + r * AST + (u << 4), src);
        }
    };
    pf(0, 0); CP_COMMIT();
    pf(1, 1); CP_COMMIT();

    // wait for Q (leave the two KV groups in flight), then load AQh frags
    CP_WAIT2();
    __syncthreads();

    const uint32_t qaddr0 = (uint32_t)((wid * 32 + (lid & 15)) * AST
                                       + ((lid >> 4) << 4));
    const uint32_t qaddr1 = qaddr0 + 16 * AST;

    uint32_t AQh[2][4][4];
#pragma unroll
    for (int kt = 0; kt < 4; kt++) {
        ldsm4(smb + qaddr0 + kt * 32, AQh[0][kt]);
        ldsm4(smb + qaddr1 + kt * 32, AQh[1][kt]);
    }
    // Q region never overwritten -> no extra barrier needed.

    const uint32_t kaddr = (uint32_t)((((lid >> 4) << 3) + (lid & 7)) * AST
                                      + (((lid >> 3) & 1) << 4));
    const uint32_t vaddr = (uint32_t)((lid & 15) * AST + ((lid >> 4) << 4));

    float o[2][8][4];
    float lsum[2][2];
#pragma unroll
    for (int bl = 0; bl < 2; bl++) {
#pragma unroll
        for (int i = 0; i < 8; i++)
#pragma unroll
            for (int e = 0; e < 4; e++) o[bl][i][e] = 0.0f;
        lsum[bl][0] = 0.0f; lsum[bl][1] = 0.0f;
    }

    const int NTILES = LL / 64;

    for (int c = 0; c < NTILES; c++) {
        CP_WAIT1();
        __syncthreads();

        const uint32_t sb  = smb + KV_OFF + (c & 1) * KVSTG;
        const uint32_t skh = sb;
        const uint32_t skl = sb + KVSUB;
        const uint32_t svh = sb + 2 * KVSUB;
        const uint32_t svl = sb + 3 * KVSUB;

        const float bias00 =
            slope * ((float)((c << 6) + 2 * (lid & 3)) - 2047.0f) - 8.0f;

        // ==== two 32-key halves: QK -> softmax -> PV per half ====
#pragma unroll
        for (int half = 0; half < 2; half++) {
            float S[2][4][4];
#pragma unroll
            for (int bl = 0; bl < 2; bl++)
#pragma unroll
                for (int i = 0; i < 4; i++)
#pragma unroll
                    for (int e = 0; e < 4; e++) S[bl][i][e] = 0.0f;

            // ---- S = Q.K^T; AQl reloaded per ks from resident smem ----
#pragma unroll
            for (int ks = 0; ks < 4; ks++) {
                uint32_t Ql0[4], Ql1[4];
                ldsm4(smb + QSUB + qaddr0 + (ks << 5), Ql0);
                ldsm4(smb + QSUB + qaddr1 + (ks << 5), Ql1);
#pragma unroll
                for (int g2 = 0; g2 < 2; g2++) {
                    const int g = half * 2 + g2;
                    uint32_t Bh[4], Bl[4];
                    uint32_t base = (g << 4) * AST + kaddr + (ks << 5);
                    ldsm4(skh + base, Bh);
                    ldsm4(skl + base, Bl);
                    mma16816(S[0][2 * g2],     AQh[0][ks], Bh);
                    mma16816(S[0][2 * g2],     AQh[0][ks], Bl);
                    mma16816(S[0][2 * g2],     Ql0,        Bh);
                    mma16816(S[0][2 * g2 + 1], AQh[0][ks], Bh + 2);
                    mma16816(S[0][2 * g2 + 1], AQh[0][ks], Bl + 2);
                    mma16816(S[0][2 * g2 + 1], Ql0,        Bh + 2);
                    mma16816(S[1][2 * g2],     AQh[1][ks], Bh);
                    mma16816(S[1][2 * g2],     AQh[1][ks], Bl);
                    mma16816(S[1][2 * g2],     Ql1,        Bh);
                    mma16816(S[1][2 * g2 + 1], AQh[1][ks], Bh + 2);
                    mma16816(S[1][2 * g2 + 1], AQh[1][ks], Bl + 2);
                    mma16816(S[1][2 * g2 + 1], Ql1,        Bh + 2);
                }
            }

            // ---- softmax (analytic max) + P -> A-fragments ----
            uint32_t PAh[2][2][4], PAl[2][2][4];
            const float biasH = bias00 + slope * (float)(half << 5);
#pragma unroll
            for (int bl = 0; bl < 2; bl++) {
#pragma unroll
                for (int nt = 0; nt < 4; nt++) {
                    const float be = biasH + slope * (float)(nt << 3);
                    const float bo = be + slope;
                    float p0 = __expf(fmaf(S[bl][nt][0], scale, be));
                    float p1 = __expf(fmaf(S[bl][nt][1], scale, bo));
                    float p2 = __expf(fmaf(S[bl][nt][2], scale, be));
                    float p3 = __expf(fmaf(S[bl][nt][3], scale, bo));
                    lsum[bl][0] += p0 + p1;
                    lsum[bl][1] += p2 + p3;
                    S[bl][nt][0] = p0; S[bl][nt][1] = p1;
                    S[bl][nt][2] = p2; S[bl][nt][3] = p3;
                }
#pragma unroll
                for (int kt2 = 0; kt2 < 2; kt2++) {
                    float p00 = S[bl][2 * kt2][0],     p01 = S[bl][2 * kt2][1];
                    float p02 = S[bl][2 * kt2][2],     p03 = S[bl][2 * kt2][3];
                    float p10 = S[bl][2 * kt2 + 1][0], p11 = S[bl][2 * kt2 + 1][1];
                    float p12 = S[bl][2 * kt2 + 1][2], p13 = S[bl][2 * kt2 + 1][3];
                    float h00 = bfhi(p00), h01 = bfhi(p01);
                    float h02 = bfhi(p02), h03 = bfhi(p03);
                    float h10 = bfhi(p10), h11 = bfhi(p11);
                    float h12 = bfhi(p12), h13 = bfhi(p13);
                    PAh[bl][kt2][0] = packbf(h00, h01);
                    PAh[bl][kt2][1] = packbf(h02, h03);
                    PAh[bl][kt2][2] = packbf(h10, h11);
                    PAh[bl][kt2][3] = packbf(h12, h13);
                    PAl[bl][kt2][0] = packbf(p00 - h00, p01 - h01);
                    PAl[bl][kt2][1] = packbf(p02 - h02, p03 - h03);
                    PAl[bl][kt2][2] = packbf(p10 - h10, p11 - h11);
                    PAl[bl][kt2][3] = packbf(p12 - h12, p13 - h13);
                }
            }

            // ---- O += P @ V for this half's 32 keys ----
#pragma unroll
            for (int dg = 0; dg < 4; dg++) {
#pragma unroll
                for (int kt2 = 0; kt2 < 2; kt2++) {
                    const int kt = half * 2 + kt2;
                    uint32_t Bvh[4], Bvl[4];
                    uint32_t base = (kt << 4) * AST + vaddr + (dg << 5);
                    ldsm4t(svh + base, Bvh);
                    ldsm4t(svl + base, Bvl);
#pragma unroll
                    for (int bl = 0; bl < 2; bl++) {
                        mma16816(o[bl][2 * dg],     PAh[bl][kt2], Bvh);
                        mma16816(o[bl][2 * dg],     PAh[bl][kt2], Bvl);
                        mma16816(o[bl][2 * dg],     PAl[bl][kt2], Bvh);
                        mma16816(o[bl][2 * dg + 1], PAh[bl][kt2], Bvh + 2);
                        mma16816(o[bl][2 * dg + 1], PAh[bl][kt2], Bvl + 2);
                        mma16816(o[bl][2 * dg + 1], PAl[bl][kt2], Bvh + 2);
                    }
                }
            }
        }

        __syncthreads();
        if (c + 2 < NTILES) pf(c + 2, c & 1);
        CP_COMMIT();
    }

    // ---- epilogue: reduce lsum across quad lanes, normalize, split ----
#pragma unroll
    for (int bl = 0; bl < 2; bl++) {
#pragma unroll
        for (int r = 0; r < 2; r++) {
            lsum[bl][r] += __shfl_xor_sync(0xffffffffu, lsum[bl][r], 1);
            lsum[bl][r] += __shfl_xor_sync(0xffffffffu, lsum[bl][r], 2);
        }
        float inv0 = 1.0f / lsum[bl][0];
        float inv1 = 1.0f / lsum[bl][1];
        const int r0 = b * LL + q0 + wid * 32 + bl * 16 + (lid >> 2);
#pragma unroll
        for (int nt = 0; nt < 8; nt++) {
            int cc = h * 64 + nt * 8 + ((lid & 3) << 1);
            float v0 = o[bl][nt][0] * inv0, v1 = o[bl][nt][1] * inv0;
            float v2 = o[bl][nt][2] * inv1, v3 = o[bl][nt][3] * inv1;
            float h0 = bfhi(v0), h1 = bfhi(v1), h2 = bfhi(v2), h3 = bfhi(v3);
            size_t oa = (size_t)r0 * 1024 + cc;
            size_t ob = (size_t)(r0 + 8) * 1024 + cc;
            *(uint32_t*)&cthi[oa] = packbf(h0, h1);
            *(uint32_t*)&ctlo[oa] = packbf(v0 - h0, v1 - h1);
            *(uint32_t*)&cthi[ob] = packbf(h2, h3);
            *(uint32_t*)&ctlo[ob] = packbf(v2 - h2, v3 - h3);
        }
    }
}

// ---------------------------------------------------------------------------
// kernel_launch: 0 prep_x  1 prep_w  2 gemm_qkv  3 attn_mma(capture)  4 gemm_o
// ---------------------------------------------------------------------------
extern "C" void kernel_launch(void* const* d_in, const int* in_sizes, int n_in,
                              void* d_out, int out_size) {
    const float* x  = (const float*)d_in[0];
    const float* Wq = (const float*)d_in[1];
    const float* Wk = (const float*)d_in[2];
    const float* Wv = (const float*)d_in[3];
    const float* Wo = (const float*)d_in[4];
    float* out = (float*)d_out;

    __nv_bfloat16 *xhi, *xlo, *cthi, *ctlo;
    __nv_bfloat16 *wqh, *wql, *wkvh, *wkvl, *woh, *wol;
    __nv_bfloat16 *aqh, *aql, *akh, *akl, *avh, *avl;
    float *ct, *st;
    cudaGetSymbolAddress((void**)&xhi,  g_xhi);
    cudaGetSymbolAddress((void**)&xlo,  g_xlo);
    cudaGetSymbolAddress((void**)&cthi, g_ctxhi);
    cudaGetSymbolAddress((void**)&ctlo, g_ctxlo);
    cudaGetSymbolAddress((void**)&wqh,  g_wqt_h);
    cudaGetSymbolAddress((void**)&wql,  g_wqt_l);
    cudaGetSymbolAddress((void**)&wkvh, g_wkvt_h);
    cudaGetSymbolAddress((void**)&wkvl, g_wkvt_l);
    cudaGetSymbolAddress((void**)&woh,  g_wot_h);
    cudaGetSymbolAddress((void**)&wol,  g_wot_l);
    cudaGetSymbolAddress((void**)&aqh,  g_qh);
    cudaGetSymbolAddress((void**)&aql,  g_ql);
    cudaGetSymbolAddress((void**)&akh,  g_kh);
    cudaGetSymbolAddress((void**)&akl,  g_kl);
    cudaGetSymbolAddress((void**)&avh,  g_vh);
    cudaGetSymbolAddress((void**)&avl,  g_vl);
    cudaGetSymbolAddress((void**)&ct,   g_cos);
    cudaGetSymbolAddress((void**)&st,   g_sin);

    const int smem_gemm = 2 * STG_BYTES;
    cudaFuncSetAttribute(gemm_qkv, cudaFuncAttributeMaxDynamicSharedMemorySize,
                         smem_gemm);
    cudaFuncSetAttribute(gemm_o, cudaFuncAttributeMaxDynamicSharedMemorySize,
                         smem_gemm);
    cudaFuncSetAttribute(attn_mma, cudaFuncAttributeMaxDynamicSharedMemorySize,
                         ATT_SMEM);

    dim3 blk(256);

    // 0: x split + rope tables
    prep_x<<<4096 + 256, blk>>>(x, xhi, xlo, ct, st);
    // 1: weight transposes+splits
    prep_w<<<2560, blk>>>(Wq, Wk, Wv, Wo, wqh, wql, wkvh, wkvl, woh, wol);

    // 2: QKV projection with fused RoPE + bf16 split epilogue
    gemm_qkv<<<dim3(12, BL / 128), blk, smem_gemm>>>(
        xhi, xlo, wqh, wql, wkvh, wkvl, aqh, aql, akh, akl, avh, avl, ct, st);

    // 3: tensor-core attention (Q-lo in smem, low-register)  <-- capture
    attn_mma<<<dim3(LL / 256, HH, BB), blk, ATT_SMEM>>>(
        aqh, aql, akh, akl, avh, avl, cthi, ctlo);

    // 4: output projection
    gemm_o<<<dim3(8, BL / 128), blk, smem_gemm>>>(
        cthi, ctlo, woh, wol, out, DD, DD);
}

// round 15
// speedup vs baseline: 1.0346x; 1.0028x over previous
#include <cuda_runtime.h>
#include <cuda_bf16.h>
#include <math.h>
#include <stdint.h>

// Problem constants
#define BB   2
#define LL   2048
#define DD   1024
#define HH   16
#define KVH  4
#define HDIM 64
#define BL   (BB * LL)    // 4096

typedef unsigned long long ull;

// ---------------------------------------------------------------------------
// mma.sync / ldmatrix / cp.async helpers (baseline PTX ISA)
// ---------------------------------------------------------------------------
__device__ __forceinline__ uint32_t smem_u32(const void* p) {
    uint32_t a;
    asm("{ .reg .u64 t; cvta.to.shared.u64 t, %1; cvt.u32.u64 %0, t; }"
        : "=r"(a) : "l"(p));
    return a;
}
__device__ __forceinline__ void ldsm4(uint32_t addr, uint32_t* r) {
    asm volatile("ldmatrix.sync.aligned.m8n8.x4.shared.b16 {%0,%1,%2,%3}, [%4];"
                 : "=r"(r[0]), "=r"(r[1]), "=r"(r[2]), "=r"(r[3]) : "r"(addr));
}
__device__ __forceinline__ void ldsm4t(uint32_t addr, uint32_t* r) {
    asm volatile("ldmatrix.sync.aligned.m8n8.x4.trans.shared.b16 {%0,%1,%2,%3}, [%4];"
                 : "=r"(r[0]), "=r"(r[1]), "=r"(r[2]), "=r"(r[3]) : "r"(addr));
}
__device__ __forceinline__ void mma16816(float* d, const uint32_t* a,
                                         const uint32_t* b) {
    asm volatile(
        "mma.sync.aligned.m16n8k16.row.col.f32.bf16.bf16.f32 "
        "{%0,%1,%2,%3}, {%4,%5,%6,%7}, {%8,%9}, {%0,%1,%2,%3};"
        : "+f"(d[0]), "+f"(d[1]), "+f"(d[2]), "+f"(d[3])
        : "r"(a[0]), "r"(a[1]), "r"(a[2]), "r"(a[3]), "r"(b[0]), "r"(b[1]));
}
__device__ __forceinline__ void cp16(uint32_t dst, const void* src) {
    asm volatile("cp.async.cg.shared.global [%0], [%1], 16;"
                 :: "r"(dst), "l"(src) : "memory");
}
#define CP_COMMIT() asm volatile("cp.async.commit_group;" ::: "memory")
#define CP_WAIT2()  asm volatile("cp.async.wait_group 2;" ::: "memory")
#define CP_WAIT1()  asm volatile("cp.async.wait_group 1;" ::: "memory")
#define CP_WAIT0()  asm volatile("cp.async.wait_group 0;" ::: "memory")

__device__ __forceinline__ uint32_t packbf(float lo, float hi) {
    __nv_bfloat162 t = __floats2bfloat162_rn(lo, hi);
    return *(uint32_t*)&t;
}
__device__ __forceinline__ float bfhi(float v) {
    return __bfloat162float(__float2bfloat16(v));
}

// ---------------------------------------------------------------------------
// Scratch (__device__ globals — no allocations allowed)
// ---------------------------------------------------------------------------
__device__ __nv_bfloat16 g_xhi[BL * DD];
__device__ __nv_bfloat16 g_xlo[BL * DD];
__device__ __nv_bfloat16 g_ctxhi[BL * DD];
__device__ __nv_bfloat16 g_ctxlo[BL * DD];
__device__ __nv_bfloat16 g_wqt_h[DD * DD];
__device__ __nv_bfloat16 g_wqt_l[DD * DD];
__device__ __nv_bfloat16 g_wkvt_h[512 * DD];
__device__ __nv_bfloat16 g_wkvt_l[512 * DD];
__device__ __nv_bfloat16 g_wot_h[DD * DD];
__device__ __nv_bfloat16 g_wot_l[DD * DD];

__device__ __nv_bfloat16 g_qh[BL * DD];
__device__ __nv_bfloat16 g_ql[BL * DD];
__device__ __nv_bfloat16 g_kh[BL * 256];
__device__ __nv_bfloat16 g_kl[BL * 256];
__device__ __nv_bfloat16 g_vh[BL * 256];
__device__ __nv_bfloat16 g_vl[BL * 256];

__device__ float g_cos[LL * 32];
__device__ float g_sin[LL * 32];

// ---------------------------------------------------------------------------
// prep_x: x split (4096 blocks) + rope tables (256 blocks)
// ---------------------------------------------------------------------------
__global__ __launch_bounds__(256)
void prep_x(const float* __restrict__ x,
            __nv_bfloat16* __restrict__ xhi, __nv_bfloat16* __restrict__ xlo,
            float* __restrict__ ct, float* __restrict__ st) {
    const int bid = blockIdx.x;
    if (bid < 4096) {
        int i = bid * 256 + threadIdx.x;
        float4 v = ((const float4*)x)[i];
        float vv[4] = {v.x, v.y, v.z, v.w};
        __nv_bfloat16 h[4], l[4];
#pragma unroll
        for (int j = 0; j < 4; j++) {
            h[j] = __float2bfloat16(vv[j]);
            l[j] = __float2bfloat16(vv[j] - __bfloat162float(h[j]));
        }
        ((uint64_t*)xhi)[i] = *(uint64_t*)h;
        ((uint64_t*)xlo)[i] = *(uint64_t*)l;
    } else {
        int i = (bid - 4096) * 256 + threadIdx.x;
        int pos = i >> 5, j = i & 31;
        float inv = powf(10000.0f, -(float)j * (1.0f / 32.0f));
        float s, c;
        sincosf((float)pos * inv, &s, &c);
        ct[i] = c;
        st[i] = s;
    }
}

// ---------------------------------------------------------------------------
// prep_w: weight transposes+splits
// ---------------------------------------------------------------------------
__global__ __launch_bounds__(256)
void prep_w(const float* __restrict__ Wq, const float* __restrict__ Wk,
            const float* __restrict__ Wv, const float* __restrict__ Wo,
            __nv_bfloat16* __restrict__ wqh, __nv_bfloat16* __restrict__ wql,
            __nv_bfloat16* __restrict__ wkvh, __nv_bfloat16* __restrict__ wkvl,
            __nv_bfloat16* __restrict__ woh, __nv_bfloat16* __restrict__ wol) {
    __shared__ float t[32][33];
    int j = blockIdx.x;
    const float* W;
    __nv_bfloat16 *hiT, *loT;
    int Nd, rowoff = 0, bx, by;
    if (j < 1024) { W = Wq; hiT = wqh; loT = wql; Nd = 1024;
                    bx = j & 31; by = j >> 5; }
    else if (j < 1536) {
        int j2 = j - 1024;
        int z = j2 >> 8;
        int r = j2 & 255;
        bx = r & 7; by = r >> 3;
        Nd = 256;
        hiT = wkvh; loT = wkvl;
        if (z == 0) { W = Wk; }
        else        { W = Wv; rowoff = 256; }
    } else {
        int j2 = j - 1536;
        W = Wo; hiT = woh; loT = wol; Nd = 1024;
        bx = j2 & 31; by = j2 >> 5;
    }
    int n0 = bx << 5, k0 = by << 5;
    int tx = threadIdx.x & 31, ty = threadIdx.x >> 5;
    for (int r = ty; r < 32; r += 8)
        t[r][tx] = W[(size_t)(k0 + r) * Nd + n0 + tx];
    __syncthreads();
    for (int r = ty; r < 32; r += 8) {
        float v = t[tx][r];
        __nv_bfloat16 h = __float2bfloat16(v);
        size_t o = (size_t)(rowoff + n0 + r) * DD + k0 + tx;
        hiT[o] = h;
        loT[o] = __float2bfloat16(v - __bfloat162float(h));
    }
}

// ---------------------------------------------------------------------------
// QKV GEMM (mma.sync bf16x3) with fused RoPE + bf16 hi/lo split epilogue.
// ---------------------------------------------------------------------------
#define STG_BYTES 40960
#define SUB_BYTES 10240

__global__ __launch_bounds__(256, 2)
void gemm_qkv(const __nv_bfloat16* __restrict__ Ahi,
              const __nv_bfloat16* __restrict__ Alo,
              const __nv_bfloat16* __restrict__ Wqh,
              const __nv_bfloat16* __restrict__ Wql,
              const __nv_bfloat16* __restrict__ Wkvh,
              const __nv_bfloat16* __restrict__ Wkvl,
              __nv_bfloat16* __restrict__ qh, __nv_bfloat16* __restrict__ ql,
              __nv_bfloat16* __restrict__ kh, __nv_bfloat16* __restrict__ kl,
              __nv_bfloat16* __restrict__ vh, __nv_bfloat16* __restrict__ vl,
              const float* __restrict__ ct, const float* __restrict__ st) {
    extern __shared__ char sm[];
    const uint32_t smb = smem_u32(sm);
    const int K = DD;

    const int tid = threadIdx.x;
    const int lid = tid & 31;
    const int wid = tid >> 5;
    const int wm  = wid >> 1;
    const int wn  = wid & 1;
    const int row0 = blockIdx.y << 7;
    const int NCH = K >> 5;

    const bool isQ = (int)blockIdx.x < 8;
    const int col0 = isQ ? (blockIdx.x << 7) : (((int)blockIdx.x - 8) << 7);
    const __nv_bfloat16* Bhi = isQ ? Wqh : Wkvh;
    const __nv_bfloat16* Blo = isQ ? Wql : Wkvl;

    const __nv_bfloat16* srcbase[4] = {Ahi, Alo, Bhi, Blo};

    auto prefetch = [&](int c, int stage) {
#pragma unroll
        for (int it = 0; it < 8; it++) {
            int i = tid + (it << 8);
            int s = i >> 9;
            int j = i & 511;
            int r = j >> 2;
            int u = j & 3;
            int grow = (s < 2 ? row0 : col0) + r;
            const __nv_bfloat16* src =
                srcbase[s] + (size_t)grow * K + (c << 5) + (u << 3);
            uint32_t dst = smb + stage * STG_BYTES + s * SUB_BYTES
                         + r * 80 + (u << 4);
            cp16(dst, src);
        }
    };

    prefetch(0, 0); CP_COMMIT();
    prefetch(1, 1); CP_COMMIT();

    float acc[2][8][4];
#pragma unroll
    for (int a = 0; a < 2; a++)
#pragma unroll
        for (int b = 0; b < 8; b++)
#pragma unroll
            for (int d = 0; d < 4; d++) acc[a][b][d] = 0.0f;

    const uint32_t aoff = (uint32_t)((wm * 32 + (lid & 15)) * 80
                                     + ((lid >> 4) << 4));
    const uint32_t boff = (uint32_t)((wn * 64 + ((lid >> 4) << 3) + (lid & 7)) * 80
                                     + (((lid >> 3) & 1) << 4));

    for (int c = 0; c < NCH; c++) {
        CP_WAIT1();
        __syncthreads();

        const uint32_t sb = smb + (c & 1) * STG_BYTES;
        const uint32_t sa_h = sb;
        const uint32_t sa_l = sb + SUB_BYTES;
        const uint32_t sb_h = sb + 2 * SUB_BYTES;
        const uint32_t sb_l = sb + 3 * SUB_BYTES;

#pragma unroll
        for (int ks = 0; ks < 2; ks++) {
            uint32_t Ah[2][4], Al[2][4];
            ldsm4(sa_h + aoff + ks * 32, Ah[0]);
            ldsm4(sa_h + aoff + 16 * 80 + ks * 32, Ah[1]);
            ldsm4(sa_l + aoff + ks * 32, Al[0]);
            ldsm4(sa_l + aoff + 16 * 80 + ks * 32, Al[1]);
#pragma unroll
            for (int g = 0; g < 4; g++) {
                uint32_t Bh[4], Bl[4];
                ldsm4(sb_h + boff + g * (16 * 80) + ks * 32, Bh);
                ldsm4(sb_l + boff + g * (16 * 80) + ks * 32, Bl);
#pragma unroll
                for (int mi = 0; mi < 2; mi++) {
                    mma16816(acc[mi][2 * g],     Ah[mi], Bh);
                    mma16816(acc[mi][2 * g],     Ah[mi], Bl);
                    mma16816(acc[mi][2 * g],     Al[mi], Bh);
                    mma16816(acc[mi][2 * g + 1], Ah[mi], Bh + 2);
                    mma16816(acc[mi][2 * g + 1], Ah[mi], Bl + 2);
                    mma16816(acc[mi][2 * g + 1], Al[mi], Bh + 2);
                }
            }
        }
        __syncthreads();
        if (c + 2 < NCH) prefetch(c + 2, c & 1);
        CP_COMMIT();
    }

    // ---- fused epilogue: RoPE (Q,K) + hi/lo split -> bf16 outputs ----
    __nv_bfloat16 *dsth, *dstl;
    int ldd, dcol0;
    bool rope;
    if (isQ)            { dsth = qh; dstl = ql; ldd = 1024; dcol0 = col0; rope = true; }
    else if (col0 < 256){ dsth = kh; dstl = kl; ldd = 256;  dcol0 = col0; rope = true; }
    else                { dsth = vh; dstl = vl; ldd = 256;  dcol0 = col0 - 256; rope = false; }

    const int rbase = row0 + wm * 32 + (lid >> 2);
#pragma unroll
    for (int mi = 0; mi < 2; mi++) {
#pragma unroll
        for (int half = 0; half < 2; half++) {
            const int row = rbase + mi * 16 + half * 8;
            const int pos = row & (LL - 1);
            const int e0 = half * 2;
            if (rope) {
#pragma unroll
                for (int ni = 0; ni < 4; ni++) {
                    const int j0 = ni * 8 + ((lid & 3) << 1);
                    float c0 = ct[pos * 32 + j0],     s0 = st[pos * 32 + j0];
                    float c1 = ct[pos * 32 + j0 + 1], s1 = st[pos * 32 + j0 + 1];
                    float x1a = acc[mi][ni][e0],     x1b = acc[mi][ni][e0 + 1];
                    float x2a = acc[mi][ni + 4][e0], x2b = acc[mi][ni + 4][e0 + 1];
                    float y1a = x1a * c0 - x2a * s0;
                    float y2a = x2a * c0 + x1a * s0;
                    float y1b = x1b * c1 - x2b * s1;
                    float y2b = x2b * c1 + x1b * s1;
                    float h1a = bfhi(y1a), h1b = bfhi(y1b);
                    float h2a = bfhi(y2a), h2b = bfhi(y2b);
                    size_t o1 = (size_t)row * ldd + dcol0 + wn * 64 + j0;
                    size_t o2 = o1 + 32;
                    *(uint32_t*)&dsth[o1] = packbf(h1a, h1b);
                    *(uint32_t*)&dstl[o1] = packbf(y1a - h1a, y1b - h1b);
                    *(uint32_t*)&dsth[o2] = packbf(h2a, h2b);
                    *(uint32_t*)&dstl[o2] = packbf(y2a - h2a, y2b - h2b);
                }
            } else {
#pragma unroll
                for (int ni = 0; ni < 8; ni++) {
                    const int j0 = ni * 8 + ((lid & 3) << 1);
                    float xa = acc[mi][ni][e0], xb = acc[mi][ni][e0 + 1];
                    float ha = bfhi(xa), hb = bfhi(xb);
                    size_t o1 = (size_t)row * ldd + dcol0 + wn * 64 + j0;
                    *(uint32_t*)&dsth[o1] = packbf(ha, hb);
                    *(uint32_t*)&dstl[o1] = packbf(xa - ha, xb - hb);
                }
            }
        }
    }
}

// ---------------------------------------------------------------------------
// Plain tensor-core GEMM for the output projection (fp32 epilogue).
// ---------------------------------------------------------------------------
__global__ __launch_bounds__(256, 2)
void gemm_o(const __nv_bfloat16* __restrict__ Ahi,
            const __nv_bfloat16* __restrict__ Alo,
            const __nv_bfloat16* __restrict__ Bhi,
            const __nv_bfloat16* __restrict__ Blo,
            float* __restrict__ C, int K, int ldc) {
    extern __shared__ char sm[];
    const uint32_t smb = smem_u32(sm);

    const int tid = threadIdx.x;
    const int lid = tid & 31;
    const int wid = tid >> 5;
    const int wm  = wid >> 1;
    const int wn  = wid & 1;
    const int row0 = blockIdx.y << 7;
    const int col0 = blockIdx.x << 7;
    const int NCH = K >> 5;

    const __nv_bfloat16* srcbase[4] = {Ahi, Alo, Bhi, Blo};

    auto prefetch = [&](int c, int stage) {
#pragma unroll
        for (int it = 0; it < 8; it++) {
            int i = tid + (it << 8);
            int s = i >> 9;
            int j = i & 511;
            int r = j >> 2;
            int u = j & 3;
            int grow = (s < 2 ? row0 : col0) + r;
            const __nv_bfloat16* src =
                srcbase[s] + (size_t)grow * K + (c << 5) + (u << 3);
            uint32_t dst = smb + stage * STG_BYTES + s * SUB_BYTES
                         + r * 80 + (u << 4);
            cp16(dst, src);
        }
    };

    prefetch(0, 0); CP_COMMIT();
    prefetch(1, 1); CP_COMMIT();

    float acc[2][8][4];
#pragma unroll
    for (int a = 0; a < 2; a++)
#pragma unroll
        for (int b = 0; b < 8; b++)
#pragma unroll
            for (int d = 0; d < 4; d++) acc[a][b][d] = 0.0f;

    const uint32_t aoff = (uint32_t)((wm * 32 + (lid & 15)) * 80
                                     + ((lid >> 4) << 4));
    const uint32_t boff = (uint32_t)((wn * 64 + ((lid >> 4) << 3) + (lid & 7)) * 80
                                     + (((lid >> 3) & 1) << 4));

    for (int c = 0; c < NCH; c++) {
        CP_WAIT1();
        __syncthreads();

        const uint32_t sb = smb + (c & 1) * STG_BYTES;
        const uint32_t sa_h = sb;
        const uint32_t sa_l = sb + SUB_BYTES;
        const uint32_t sb_h = sb + 2 * SUB_BYTES;
        const uint32_t sb_l = sb + 3 * SUB_BYTES;

#pragma unroll
        for (int ks = 0; ks < 2; ks++) {
            uint32_t Ah[2][4], Al[2][4];
            ldsm4(sa_h + aoff + ks * 32, Ah[0]);
            ldsm4(sa_h + aoff + 16 * 80 + ks * 32, Ah[1]);
            ldsm4(sa_l + aoff + ks * 32, Al[0]);
            ldsm4(sa_l + aoff + 16 * 80 + ks * 32, Al[1]);
#pragma unroll
            for (int g = 0; g < 4; g++) {
                uint32_t Bh[4], Bl[4];
                ldsm4(sb_h + boff + g * (16 * 80) + ks * 32, Bh);
                ldsm4(sb_l + boff + g * (16 * 80) + ks * 32, Bl);
#pragma unroll
                for (int mi = 0; mi < 2; mi++) {
                    mma16816(acc[mi][2 * g],     Ah[mi], Bh);
                    mma16816(acc[mi][2 * g],     Ah[mi], Bl);
                    mma16816(acc[mi][2 * g],     Al[mi], Bh);
                    mma16816(acc[mi][2 * g + 1], Ah[mi], Bh + 2);
                    mma16816(acc[mi][2 * g + 1], Ah[mi], Bl + 2);
                    mma16816(acc[mi][2 * g + 1], Al[mi], Bh + 2);
                }
            }
        }
        __syncthreads();
        if (c + 2 < NCH) prefetch(c + 2, c & 1);
        CP_COMMIT();
    }

#pragma unroll
    for (int mi = 0; mi < 2; mi++) {
        int r0 = row0 + wm * 32 + mi * 16 + (lid >> 2);
#pragma unroll
        for (int ni = 0; ni < 8; ni++) {
            int cc = col0 + wn * 64 + ni * 8 + ((lid & 3) << 1);
            float2 v0; v0.x = acc[mi][ni][0]; v0.y = acc[mi][ni][1];
            float2 v1; v1.x = acc[mi][ni][2]; v1.y = acc[mi][ni][3];
            *(float2*)(C + (size_t)r0 * ldc + cc)       = v0;
            *(float2*)(C + (size_t)(r0 + 8) * ldc + cc) = v1;
        }
    }
}

// ---------------------------------------------------------------------------
// Tensor-core flash attention v4: OCCUPANCY 2.
// 128 q-rows/CTA (8 warps x 16 rows), 32-key KV tiles, 2-stage pipeline.
// Q permanent in smem; AQh in regs; AQl re-ldsm'd per ks.
// smem/CTA: Q 36864 + 2*KV 36864 = 73728 -> 2 CTAs/SM. Regs capped at 128.
// ---------------------------------------------------------------------------
#define AST 144
#define KVSUB32 (32 * AST)          // 4608
#define KVSTG32 (4 * KVSUB32)       // 18432
#define QSUB32  (128 * AST)         // 18432
#define KV_OFF32 (2 * QSUB32)       // 36864
#define ATT_SMEM (KV_OFF32 + 2 * KVSTG32)   // 73728

__global__ __launch_bounds__(256, 2)
void attn_mma(const __nv_bfloat16* __restrict__ qh, const __nv_bfloat16* __restrict__ ql,
              const __nv_bfloat16* __restrict__ kh, const __nv_bfloat16* __restrict__ kl,
              const __nv_bfloat16* __restrict__ vh, const __nv_bfloat16* __restrict__ vl,
              __nv_bfloat16* __restrict__ cthi, __nv_bfloat16* __restrict__ ctlo) {
    extern __shared__ char sm[];
    const uint32_t smb = smem_u32(sm);

    const int tid = threadIdx.x;
    const int lid = tid & 31;
    const int wid = tid >> 5;
    const int q0  = blockIdx.x << 7;           // 128-row q tile
    const int h   = blockIdx.y;
    const int b   = blockIdx.z;
    const int kvh2 = h >> 2;

    const float slope = exp2f(-0.5f * (float)(h + 1));
    const float scale = 0.125f;

    // ---- stage Q into permanent smem (hi @0, lo @QSUB32): 8 cp16/thread ----
#pragma unroll
    for (int t = 0; t < 8; t++) {
        int i = tid + (t << 8);                // 0..2047
        int s = i >> 10;                       // 0: hi, 1: lo
        int j = i & 1023;
        int r = j >> 3;                        // row 0..127
        int u = j & 7;
        const __nv_bfloat16* src =
            (s ? ql : qh) + (size_t)(b * LL + q0 + r) * 1024 + h * 64 + (u << 3);
        cp16(smb + s * QSUB32 + r * AST + (u << 4), src);
    }
    CP_COMMIT();

    // ---- KV pipeline (2 stages of 32 keys): 4 cp16/thread per tile ----
    const __nv_bfloat16* kvsrc[4] = {kh, kl, vh, vl};
    auto pf = [&](int c, int st) {
#pragma unroll
        for (int t = 0; t < 4; t++) {
            int i = tid + (t << 8);            // 0..1023
            int s = i >> 8;                    // subtile 0..3
            int j = i & 255;
            int r = j >> 3;                    // row 0..31
            int u = j & 7;
            const __nv_bfloat16* src =
                kvsrc[s] + (size_t)(b * LL + (c << 5) + r) * 256 + kvh2 * 64 + (u << 3);
            cp16(smb + KV_OFF32 + st * KVSTG32 + s * KVSUB32 + r * AST + (u << 4), src);
        }
    };
    pf(0, 0); CP_COMMIT();
    pf(1, 1); CP_COMMIT();

    // wait for Q (two KV groups still in flight), load AQh fragments
    CP_WAIT2();
    __syncthreads();

    const uint32_t qaddr = (uint32_t)((wid * 16 + (lid & 15)) * AST
                                      + ((lid >> 4) << 4));
    uint32_t AQh[4][4];
#pragma unroll
    for (int kt = 0; kt < 4; kt++)
        ldsm4(smb + qaddr + kt * 32, AQh[kt]);
    // Q region never overwritten -> no extra barrier.

    const uint32_t kaddr = (uint32_t)((((lid >> 4) << 3) + (lid & 7)) * AST
                                      + (((lid >> 3) & 1) << 4));
    const uint32_t vaddr = (uint32_t)((lid & 15) * AST + ((lid >> 4) << 4));

    float o[8][4];
    float lsum[2];
#pragma unroll
    for (int i = 0; i < 8; i++)
#pragma unroll
        for (int e = 0; e < 4; e++) o[i][e] = 0.0f;
    lsum[0] = 0.0f; lsum[1] = 0.0f;

    const int NTILES = LL / 32;   // 64

    for (int c = 0; c < NTILES; c++) {
        CP_WAIT1();
        __syncthreads();

        const uint32_t sb  = smb + KV_OFF32 + (c & 1) * KVSTG32;
        const uint32_t skh = sb;
        const uint32_t skl = sb + KVSUB32;
        const uint32_t svh = sb + 2 * KVSUB32;
        const uint32_t svl = sb + 3 * KVSUB32;

        // ---- S = Q.K^T (32 keys = 4 n8 tiles); AQl reloaded per ks ----
        float S[4][4];
#pragma unroll
        for (int i = 0; i < 4; i++)
#pragma unroll
            for (int e = 0; e < 4; e++) S[i][e] = 0.0f;

#pragma unroll
        for (int ks = 0; ks < 4; ks++) {
            uint32_t Ql[4];
            ldsm4(smb + QSUB32 + qaddr + (ks << 5), Ql);
#pragma unroll
            for (int g = 0; g < 2; g++) {
                uint32_t Bh[4], Bl[4];
                uint32_t base = (g << 4) * AST + kaddr + (ks << 5);
                ldsm4(skh + base, Bh);
                ldsm4(skl + base, Bl);
                mma16816(S[2 * g],     AQh[ks], Bh);
                mma16816(S[2 * g],     AQh[ks], Bl);
                mma16816(S[2 * g],     Ql,      Bh);
                mma16816(S[2 * g + 1], AQh[ks], Bh + 2);
                mma16816(S[2 * g + 1], AQh[ks], Bl + 2);
                mma16816(S[2 * g + 1], Ql,      Bh + 2);
            }
        }

        // ---- softmax with analytic max bound (q-independent bias) ----
        const float bias00 =
            slope * ((float)((c << 5) + 2 * (lid & 3)) - 2047.0f) - 8.0f;
        uint32_t PAh[2][4], PAl[2][4];
#pragma unroll
        for (int nt = 0; nt < 4; nt++) {
            const float be = bias00 + slope * (float)(nt << 3);
            const float bo = be + slope;
            float p0 = __expf(fmaf(S[nt][0], scale, be));
            float p1 = __expf(fmaf(S[nt][1], scale, bo));
            float p2 = __expf(fmaf(S[nt][2], scale, be));
            float p3 = __expf(fmaf(S[nt][3], scale, bo));
            lsum[0] += p0 + p1;
            lsum[1] += p2 + p3;
            S[nt][0] = p0; S[nt][1] = p1;
            S[nt][2] = p2; S[nt][3] = p3;
        }
#pragma unroll
        for (int kt = 0; kt < 2; kt++) {
            float p00 = S[2 * kt][0],     p01 = S[2 * kt][1];
            float p02 = S[2 * kt][2],     p03 = S[2 * kt][3];
            float p10 = S[2 * kt + 1][0], p11 = S[2 * kt + 1][1];
            float p12 = S[2 * kt + 1][2], p13 = S[2 * kt + 1][3];
            float h00 = bfhi(p00), h01 = bfhi(p01), h02 = bfhi(p02), h03 = bfhi(p03);
            float h10 = bfhi(p10), h11 = bfhi(p11), h12 = bfhi(p12), h13 = bfhi(p13);
            PAh[kt][0] = packbf(h00, h01);
            PAh[kt][1] = packbf(h02, h03);
            PAh[kt][2] = packbf(h10, h11);
            PAh[kt][3] = packbf(h12, h13);
            PAl[kt][0] = packbf(p00 - h00, p01 - h01);
            PAl[kt][1] = packbf(p02 - h02, p03 - h03);
            PAl[kt][2] = packbf(p10 - h10, p11 - h11);
            PAl[kt][3] = packbf(p12 - h12, p13 - h13);
        }

        // ---- O += P @ V (32 keys = 2 kt groups) ----
#pragma unroll
        for (int dg = 0; dg < 4; dg++) {
#pragma unroll
            for (int kt = 0; kt < 2; kt++) {
                uint32_t Bvh[4], Bvl[4];
                uint32_t base = (kt << 4) * AST + vaddr + (dg << 5);
                ldsm4t(svh + base, Bvh);
                ldsm4t(svl + base, Bvl);
                mma16816(o[2 * dg],     PAh[kt], Bvh);
                mma16816(o[2 * dg],     PAh[kt], Bvl);
                mma16816(o[2 * dg],     PAl[kt], Bvh);
                mma16816(o[2 * dg + 1], PAh[kt], Bvh + 2);
                mma16816(o[2 * dg + 1], PAh[kt], Bvl + 2);
                mma16816(o[2 * dg + 1], PAl[kt], Bvh + 2);
            }
        }

        __syncthreads();
        if (c + 2 < NTILES) pf(c + 2, c & 1);
        CP_COMMIT();
    }

    // ---- epilogue: reduce lsum across quad lanes, normalize, split ----
#pragma unroll
    for (int r = 0; r < 2; r++) {
        lsum[r] += __shfl_xor_sync(0xffffffffu, lsum[r], 1);
        lsum[r] += __shfl_xor_sync(0xffffffffu, lsum[r], 2);
    }
    float inv0 = 1.0f / lsum[0];
    float inv1 = 1.0f / lsum[1];
    const int r0 = b * LL + q0 + wid * 16 + (lid >> 2);
#pragma unroll
    for (int nt = 0; nt < 8; nt++) {
        int cc = h * 64 + nt * 8 + ((lid & 3) << 1);
        float v0 = o[nt][0] * inv0, v1 = o[nt][1] * inv0;
        float v2 = o[nt][2] * inv1, v3 = o[nt][3] * inv1;
        float h0 = bfhi(v0), h1 = bfhi(v1), h2 = bfhi(v2), h3 = bfhi(v3);
        size_t oa = (size_t)r0 * 1024 + cc;
        size_t ob = (size_t)(r0 + 8) * 1024 + cc;
        *(uint32_t*)&cthi[oa] = packbf(h0, h1);
        *(uint32_t*)&ctlo[oa] = packbf(v0 - h0, v1 - h1);
        *(uint32_t*)&cthi[ob] = packbf(h2, h3);
        *(uint32_t*)&ctlo[ob] = packbf(v2 - h2, v3 - h3);
    }
}

// ---------------------------------------------------------------------------
// kernel_launch: 0 prep_x  1 prep_w  2 gemm_qkv  3 attn_mma(capture)  4 gemm_o
// ---------------------------------------------------------------------------
extern "C" void kernel_launch(void* const* d_in, const int* in_sizes, int n_in,
                              void* d_out, int out_size) {
    const float* x  = (const float*)d_in[0];
    const float* Wq = (const float*)d_in[1];
    const float* Wk = (const float*)d_in[2];
    const float* Wv = (const float*)d_in[3];
    const float* Wo = (const float*)d_in[4];
    float* out = (float*)d_out;

    __nv_bfloat16 *xhi, *xlo, *cthi, *ctlo;
    __nv_bfloat16 *wqh, *wql, *wkvh, *wkvl, *woh, *wol;
    __nv_bfloat16 *aqh, *aql, *akh, *akl, *avh, *avl;
    float *ct, *st;
    cudaGetSymbolAddress((void**)&xhi,  g_xhi);
    cudaGetSymbolAddress((void**)&xlo,  g_xlo);
    cudaGetSymbolAddress((void**)&cthi, g_ctxhi);
    cudaGetSymbolAddress((void**)&ctlo, g_ctxlo);
    cudaGetSymbolAddress((void**)&wqh,  g_wqt_h);
    cudaGetSymbolAddress((void**)&wql,  g_wqt_l);
    cudaGetSymbolAddress((void**)&wkvh, g_wkvt_h);
    cudaGetSymbolAddress((void**)&wkvl, g_wkvt_l);
    cudaGetSymbolAddress((void**)&woh,  g_wot_h);
    cudaGetSymbolAddress((void**)&wol,  g_wot_l);
    cudaGetSymbolAddress((void**)&aqh,  g_qh);
    cudaGetSymbolAddress((void**)&aql,  g_ql);
    cudaGetSymbolAddress((void**)&akh,  g_kh);
    cudaGetSymbolAddress((void**)&akl,  g_kl);
    cudaGetSymbolAddress((void**)&avh,  g_vh);
    cudaGetSymbolAddress((void**)&avl,  g_vl);
    cudaGetSymbolAddress((void**)&ct,   g_cos);
    cudaGetSymbolAddress((void**)&st,   g_sin);

    const int smem_gemm = 2 * STG_BYTES;
    cudaFuncSetAttribute(gemm_qkv, cudaFuncAttributeMaxDynamicSharedMemorySize,
                         smem_gemm);
    cudaFuncSetAttribute(gemm_o, cudaFuncAttributeMaxDynamicSharedMemorySize,
                         smem_gemm);
    cudaFuncSetAttribute(attn_mma, cudaFuncAttributeMaxDynamicSharedMemorySize,
                         ATT_SMEM);

    dim3 blk(256);

    // 0: x split + rope tables
    prep_x<<<4096 + 256, blk>>>(x, xhi, xlo, ct, st);
    // 1: weight transposes+splits
    prep_w<<<2560, blk>>>(Wq, Wk, Wv, Wo, wqh, wql, wkvh, wkvl, woh, wol);

    // 2: QKV projection with fused RoPE + bf16 split epilogue
    gemm_qkv<<<dim3(12, BL / 128), blk, smem_gemm>>>(
        xhi, xlo, wqh, wql, wkvh, wkvl, aqh, aql, akh, akl, avh, avl, ct, st);

    // 3: tensor-core attention (128 q-rows, occ 2)  <-- capture slot
    attn_mma<<<dim3(LL / 128, HH, BB), blk, ATT_SMEM>>>(
        aqh, aql, akh, akl, avh, avl, cthi, ctlo);

    // 4: output projection
    gemm_o<<<dim3(8, BL / 128), blk, smem_gemm>>>(
        cthi, ctlo, woh, wol, out, DD, DD);
}

// round 16
// speedup vs baseline: 1.5000x; 1.4499x over previous
#include <cuda_runtime.h>
#include <cuda_fp16.h>
#include <math.h>
#include <stdint.h>

// Problem constants
#define BB   2
#define LL   2048
#define DD   1024
#define HH   16
#define KVH  4
#define HDIM 64
#define BL   (BB * LL)    // 4096

typedef unsigned long long ull;

// ---------------------------------------------------------------------------
// mma.sync / ldmatrix / cp.async helpers (baseline PTX ISA)
// ---------------------------------------------------------------------------
__device__ __forceinline__ uint32_t smem_u32(const void* p) {
    uint32_t a;
    asm("{ .reg .u64 t; cvta.to.shared.u64 t, %1; cvt.u32.u64 %0, t; }"
        : "=r"(a) : "l"(p));
    return a;
}
__device__ __forceinline__ void ldsm4(uint32_t addr, uint32_t* r) {
    asm volatile("ldmatrix.sync.aligned.m8n8.x4.shared.b16 {%0,%1,%2,%3}, [%4];"
                 : "=r"(r[0]), "=r"(r[1]), "=r"(r[2]), "=r"(r[3]) : "r"(addr));
}
__device__ __forceinline__ void ldsm4t(uint32_t addr, uint32_t* r) {
    asm volatile("ldmatrix.sync.aligned.m8n8.x4.trans.shared.b16 {%0,%1,%2,%3}, [%4];"
                 : "=r"(r[0]), "=r"(r[1]), "=r"(r[2]), "=r"(r[3]) : "r"(addr));
}
__device__ __forceinline__ void mma16816(float* d, const uint32_t* a,
                                         const uint32_t* b) {
    asm volatile(
        "mma.sync.aligned.m16n8k16.row.col.f32.f16.f16.f32 "
        "{%0,%1,%2,%3}, {%4,%5,%6,%7}, {%8,%9}, {%0,%1,%2,%3};"
        : "+f"(d[0]), "+f"(d[1]), "+f"(d[2]), "+f"(d[3])
        : "r"(a[0]), "r"(a[1]), "r"(a[2]), "r"(a[3]), "r"(b[0]), "r"(b[1]));
}
__device__ __forceinline__ void cp16(uint32_t dst, const void* src) {
    asm volatile("cp.async.cg.shared.global [%0], [%1], 16;"
                 :: "r"(dst), "l"(src) : "memory");
}
#define CP_COMMIT() asm volatile("cp.async.commit_group;" ::: "memory")
#define CP_WAIT2()  asm volatile("cp.async.wait_group 2;" ::: "memory")
#define CP_WAIT1()  asm volatile("cp.async.wait_group 1;" ::: "memory")

__device__ __forceinline__ uint32_t packh(float a, float b) {
    __half2 t = __floats2half2_rn(a, b);
    return *(uint32_t*)&t;
}
__device__ __forceinline__ float hhi(float v) {
    return __half2float(__float2half(v));
}

// ---------------------------------------------------------------------------
// Scratch (__device__ globals — no allocations allowed)
// ---------------------------------------------------------------------------
__device__ __half g_xhi[BL * DD];
__device__ __half g_xlo[BL * DD];
__device__ __half g_ctxhi[BL * DD];
__device__ __half g_ctxlo[BL * DD];
__device__ __half g_wqt[DD * DD];       // single fp16 (B side)
__device__ __half g_wkvt[512 * DD];
__device__ __half g_wot[DD * DD];

__device__ __half g_qh[BL * DD];        // Q split hi/lo
__device__ __half g_ql[BL * DD];
__device__ __half g_kh[BL * 256];       // K single
__device__ __half g_vh[BL * 256];       // V single

__device__ float g_cos[LL * 32];
__device__ float g_sin[LL * 32];

// ---------------------------------------------------------------------------
// prep_x: x fp32 -> fp16 hi/lo split (4096 blocks) + rope tables (256 blocks)
// ---------------------------------------------------------------------------
__global__ __launch_bounds__(256)
void prep_x(const float* __restrict__ x,
            __half* __restrict__ xhi, __half* __restrict__ xlo,
            float* __restrict__ ct, float* __restrict__ st) {
    const int bid = blockIdx.x;
    if (bid < 4096) {
        int i = bid * 256 + threadIdx.x;
        float4 v = ((const float4*)x)[i];
        float vv[4] = {v.x, v.y, v.z, v.w};
        __half h[4], l[4];
#pragma unroll
        for (int j = 0; j < 4; j++) {
            h[j] = __float2half(vv[j]);
            l[j] = __float2half(vv[j] - __half2float(h[j]));
        }
        ((uint64_t*)xhi)[i] = *(uint64_t*)h;
        ((uint64_t*)xlo)[i] = *(uint64_t*)l;
    } else {
        int i = (bid - 4096) * 256 + threadIdx.x;
        int pos = i >> 5, j = i & 31;
        float inv = powf(10000.0f, -(float)j * (1.0f / 32.0f));
        float s, c;
        sincosf((float)pos * inv, &s, &c);
        ct[i] = c;
        st[i] = s;
    }
}

// ---------------------------------------------------------------------------
// prep_w: weight transposes -> single fp16
// ---------------------------------------------------------------------------
__global__ __launch_bounds__(256)
void prep_w(const float* __restrict__ Wq, const float* __restrict__ Wk,
            const float* __restrict__ Wv, const float* __restrict__ Wo,
            __half* __restrict__ wq, __half* __restrict__ wkv,
            __half* __restrict__ wo) {
    __shared__ float t[32][33];
    int j = blockIdx.x;
    const float* W;
    __half* outT;
    int Nd, rowoff = 0, bx, by;
    if (j < 1024) { W = Wq; outT = wq; Nd = 1024;
                    bx = j & 31; by = j >> 5; }
    else if (j < 1536) {
        int j2 = j - 1024;
        int z = j2 >> 8;
        int r = j2 & 255;
        bx = r & 7; by = r >> 3;
        Nd = 256;
        outT = wkv;
        if (z == 0) { W = Wk; }
        else        { W = Wv; rowoff = 256; }
    } else {
        int j2 = j - 1536;
        W = Wo; outT = wo; Nd = 1024;
        bx = j2 & 31; by = j2 >> 5;
    }
    int n0 = bx << 5, k0 = by << 5;
    int tx = threadIdx.x & 31, ty = threadIdx.x >> 5;
    for (int r = ty; r < 32; r += 8)
        t[r][tx] = W[(size_t)(k0 + r) * Nd + n0 + tx];
    __syncthreads();
    for (int r = ty; r < 32; r += 8)
        outT[(size_t)(rowoff + n0 + r) * DD + k0 + tx] = __float2half(t[tx][r]);
}

// ---------------------------------------------------------------------------
// fp16 2-term GEMM core macro pieces: A = hi/lo fp16, B = single fp16.
// smem per stage: A_hi(10240) + A_lo(10240) + B(10240) = 30720.
// ---------------------------------------------------------------------------
#define SUB3 10240
#define STG3 30720

// ---------------------------------------------------------------------------
// QKV GEMM with fused RoPE + fp16 split epilogue.
// grid (12, 32): bx<8 -> Q; 8..9 -> K; 10..11 -> V.
// ---------------------------------------------------------------------------
__global__ __launch_bounds__(256, 2)
void gemm_qkv(const __half* __restrict__ Ahi, const __half* __restrict__ Alo,
              const __half* __restrict__ Wq, const __half* __restrict__ Wkv,
              __half* __restrict__ qh, __half* __restrict__ ql,
              __half* __restrict__ kh, __half* __restrict__ vh,
              const float* __restrict__ ct, const float* __restrict__ st) {
    extern __shared__ char sm[];
    const uint32_t smb = smem_u32(sm);
    const int K = DD;

    const int tid = threadIdx.x;
    const int lid = tid & 31;
    const int wid = tid >> 5;
    const int wm  = wid >> 1;
    const int wn  = wid & 1;
    const int row0 = blockIdx.y << 7;
    const int NCH = K >> 5;

    const bool isQ = (int)blockIdx.x < 8;
    const int col0 = isQ ? (blockIdx.x << 7) : (((int)blockIdx.x - 8) << 7);
    const __half* B = isQ ? Wq : Wkv;

    const __half* srcbase[3] = {Ahi, Alo, B};

    auto prefetch = [&](int c, int stage) {
#pragma unroll
        for (int it = 0; it < 6; it++) {
            int i = tid + (it << 8);          // 0..1535
            int s = i >> 9;                   // 0..2
            int j = i & 511;
            int r = j >> 2;
            int u = j & 3;
            int grow = (s < 2 ? row0 : col0) + r;
            const __half* src =
                srcbase[s] + (size_t)grow * K + (c << 5) + (u << 3);
            uint32_t dst = smb + stage * STG3 + s * SUB3 + r * 80 + (u << 4);
            cp16(dst, src);
        }
    };

    prefetch(0, 0); CP_COMMIT();
    prefetch(1, 1); CP_COMMIT();

    float acc[2][8][4];
#pragma unroll
    for (int a = 0; a < 2; a++)
#pragma unroll
        for (int b = 0; b < 8; b++)
#pragma unroll
            for (int d = 0; d < 4; d++) acc[a][b][d] = 0.0f;

    const uint32_t aoff = (uint32_t)((wm * 32 + (lid & 15)) * 80
                                     + ((lid >> 4) << 4));
    const uint32_t boff = (uint32_t)((wn * 64 + ((lid >> 4) << 3) + (lid & 7)) * 80
                                     + (((lid >> 3) & 1) << 4));

    for (int c = 0; c < NCH; c++) {
        CP_WAIT1();
        __syncthreads();

        const uint32_t sb = smb + (c & 1) * STG3;
        const uint32_t sa_h = sb;
        const uint32_t sa_l = sb + SUB3;
        const uint32_t sb_b = sb + 2 * SUB3;

#pragma unroll
        for (int ks = 0; ks < 2; ks++) {
            uint32_t Ah[2][4], Al[2][4];
            ldsm4(sa_h + aoff + ks * 32, Ah[0]);
            ldsm4(sa_h + aoff + 16 * 80 + ks * 32, Ah[1]);
            ldsm4(sa_l + aoff + ks * 32, Al[0]);
            ldsm4(sa_l + aoff + 16 * 80 + ks * 32, Al[1]);
#pragma unroll
            for (int g = 0; g < 4; g++) {
                uint32_t Bf[4];
                ldsm4(sb_b + boff + g * (16 * 80) + ks * 32, Bf);
#pragma unroll
                for (int mi = 0; mi < 2; mi++) {
                    mma16816(acc[mi][2 * g],     Ah[mi], Bf);
                    mma16816(acc[mi][2 * g],     Al[mi], Bf);
                    mma16816(acc[mi][2 * g + 1], Ah[mi], Bf + 2);
                    mma16816(acc[mi][2 * g + 1], Al[mi], Bf + 2);
                }
            }
        }
        __syncthreads();
        if (c + 2 < NCH) prefetch(c + 2, c & 1);
        CP_COMMIT();
    }

    // ---- fused epilogue: RoPE (Q,K) -> Q split fp16, K/V single fp16 ----
    const int rbase = row0 + wm * 32 + (lid >> 2);
    const int mode = isQ ? 0 : (col0 < 256 ? 1 : 2);   // 0:Q 1:K 2:V
    const int ldd = isQ ? 1024 : 256;
    const int dcol0 = (mode == 2) ? col0 - 256 : col0;

#pragma unroll
    for (int mi = 0; mi < 2; mi++) {
#pragma unroll
        for (int half = 0; half < 2; half++) {
            const int row = rbase + mi * 16 + half * 8;
            const int pos = row & (LL - 1);
            const int e0 = half * 2;
            if (mode == 2) {   // V: single fp16, no rope
#pragma unroll
                for (int ni = 0; ni < 8; ni++) {
                    const int j0 = ni * 8 + ((lid & 3) << 1);
                    size_t o1 = (size_t)row * ldd + dcol0 + wn * 64 + j0;
                    *(uint32_t*)&vh[o1] =
                        packh(acc[mi][ni][e0], acc[mi][ni][e0 + 1]);
                }
            } else {           // Q or K: rope
#pragma unroll
                for (int ni = 0; ni < 4; ni++) {
                    const int j0 = ni * 8 + ((lid & 3) << 1);
                    float c0 = ct[pos * 32 + j0],     s0 = st[pos * 32 + j0];
                    float c1 = ct[pos * 32 + j0 + 1], s1 = st[pos * 32 + j0 + 1];
                    float x1a = acc[mi][ni][e0],     x1b = acc[mi][ni][e0 + 1];
                    float x2a = acc[mi][ni + 4][e0], x2b = acc[mi][ni + 4][e0 + 1];
                    float y1a = x1a * c0 - x2a * s0;
                    float y2a = x2a * c0 + x1a * s0;
                    float y1b = x1b * c1 - x2b * s1;
                    float y2b = x2b * c1 + x1b * s1;
                    size_t o1 = (size_t)row * ldd + dcol0 + wn * 64 + j0;
                    size_t o2 = o1 + 32;
                    if (mode == 0) {   // Q: hi/lo split
                        float h1a = hhi(y1a), h1b = hhi(y1b);
                        float h2a = hhi(y2a), h2b = hhi(y2b);
                        *(uint32_t*)&qh[o1] = packh(h1a, h1b);
                        *(uint32_t*)&ql[o1] = packh(y1a - h1a, y1b - h1b);
                        *(uint32_t*)&qh[o2] = packh(h2a, h2b);
                        *(uint32_t*)&ql[o2] = packh(y2a - h2a, y2b - h2b);
                    } else {           // K: single
                        *(uint32_t*)&kh[o1] = packh(y1a, y1b);
                        *(uint32_t*)&kh[o2] = packh(y2a, y2b);
                    }
                }
            }
        }
    }
}

// ---------------------------------------------------------------------------
// Output projection GEMM: A = ctx hi/lo fp16, B = Wo single fp16, fp32 out.
// ---------------------------------------------------------------------------
__global__ __launch_bounds__(256, 2)
void gemm_o(const __half* __restrict__ Ahi, const __half* __restrict__ Alo,
            const __half* __restrict__ B, float* __restrict__ C,
            int K, int ldc) {
    extern __shared__ char sm[];
    const uint32_t smb = smem_u32(sm);

    const int tid = threadIdx.x;
    const int lid = tid & 31;
    const int wid = tid >> 5;
    const int wm  = wid >> 1;
    const int wn  = wid & 1;
    const int row0 = blockIdx.y << 7;
    const int col0 = blockIdx.x << 7;
    const int NCH = K >> 5;

    const __half* srcbase[3] = {Ahi, Alo, B};

    auto prefetch = [&](int c, int stage) {
#pragma unroll
        for (int it = 0; it < 6; it++) {
            int i = tid + (it << 8);
            int s = i >> 9;
            int j = i & 511;
            int r = j >> 2;
            int u = j & 3;
            int grow = (s < 2 ? row0 : col0) + r;
            const __half* src =
                srcbase[s] + (size_t)grow * K + (c << 5) + (u << 3);
            uint32_t dst = smb + stage * STG3 + s * SUB3 + r * 80 + (u << 4);
            cp16(dst, src);
        }
    };

    prefetch(0, 0); CP_COMMIT();
    prefetch(1, 1); CP_COMMIT();

    float acc[2][8][4];
#pragma unroll
    for (int a = 0; a < 2; a++)
#pragma unroll
        for (int b = 0; b < 8; b++)
#pragma unroll
            for (int d = 0; d < 4; d++) acc[a][b][d] = 0.0f;

    const uint32_t aoff = (uint32_t)((wm * 32 + (lid & 15)) * 80
                                     + ((lid >> 4) << 4));
    const uint32_t boff = (uint32_t)((wn * 64 + ((lid >> 4) << 3) + (lid & 7)) * 80
                                     + (((lid >> 3) & 1) << 4));

    for (int c = 0; c < NCH; c++) {
        CP_WAIT1();
        __syncthreads();

        const uint32_t sb = smb + (c & 1) * STG3;
        const uint32_t sa_h = sb;
        const uint32_t sa_l = sb + SUB3;
        const uint32_t sb_b = sb + 2 * SUB3;

#pragma unroll
        for (int ks = 0; ks < 2; ks++) {
            uint32_t Ah[2][4], Al[2][4];
            ldsm4(sa_h + aoff + ks * 32, Ah[0]);
            ldsm4(sa_h + aoff + 16 * 80 + ks * 32, Ah[1]);
            ldsm4(sa_l + aoff + ks * 32, Al[0]);
            ldsm4(sa_l + aoff + 16 * 80 + ks * 32, Al[1]);
#pragma unroll
            for (int g = 0; g < 4; g++) {
                uint32_t Bf[4];
                ldsm4(sb_b + boff + g * (16 * 80) + ks * 32, Bf);
#pragma unroll
                for (int mi = 0; mi < 2; mi++) {
                    mma16816(acc[mi][2 * g],     Ah[mi], Bf);
                    mma16816(acc[mi][2 * g],     Al[mi], Bf);
                    mma16816(acc[mi][2 * g + 1], Ah[mi], Bf + 2);
                    mma16816(acc[mi][2 * g + 1], Al[mi], Bf + 2);
                }
            }
        }
        __syncthreads();
        if (c + 2 < NCH) prefetch(c + 2, c & 1);
        CP_COMMIT();
    }

#pragma unroll
    for (int mi = 0; mi < 2; mi++) {
        int r0 = row0 + wm * 32 + mi * 16 + (lid >> 2);
#pragma unroll
        for (int ni = 0; ni < 8; ni++) {
            int cc = col0 + wn * 64 + ni * 8 + ((lid & 3) << 1);
            float2 v0; v0.x = acc[mi][ni][0]; v0.y = acc[mi][ni][1];
            float2 v1; v1.x = acc[mi][ni][2]; v1.y = acc[mi][ni][3];
            *(float2*)(C + (size_t)r0 * ldc + cc)       = v0;
            *(float2*)(C + (size_t)(r0 + 8) * ldc + cc) = v1;
        }
    }
}

// ---------------------------------------------------------------------------
// Flash attention, fp16 2-term: Q split (hi regs, lo re-ldsm'd), K/V single.
// 128 q-rows/CTA, 32-key tiles, 2-stage pipeline, occ 2, analytic-max softmax.
// smem: Qhi 18432 + Qlo 18432 + 2*(K 4608 + V 4608) = 55296.
// ---------------------------------------------------------------------------
#define AST 144
#define KVSUB (32 * AST)           // 4608
#define KVSTG (2 * KVSUB)          // 9216
#define QSUB  (128 * AST)          // 18432
#define KV_OFF (2 * QSUB)          // 36864
#define ATT_SMEM (KV_OFF + 2 * KVSTG)   // 55296

__global__ __launch_bounds__(256, 2)
void attn_mma(const __half* __restrict__ qh, const __half* __restrict__ ql,
              const __half* __restrict__ kh, const __half* __restrict__ vh,
              __half* __restrict__ cthi, __half* __restrict__ ctlo) {
    extern __shared__ char sm[];
    const uint32_t smb = smem_u32(sm);

    const int tid = threadIdx.x;
    const int lid = tid & 31;
    const int wid = tid >> 5;
    const int q0  = blockIdx.x << 7;
    const int h   = blockIdx.y;
    const int b   = blockIdx.z;
    const int kvh2 = h >> 2;

    const float slope = exp2f(-0.5f * (float)(h + 1));
    const float scale = 0.125f;

    // ---- stage Q into permanent smem (hi @0, lo @QSUB) ----
#pragma unroll
    for (int t = 0; t < 8; t++) {
        int i = tid + (t << 8);
        int s = i >> 10;
        int j = i & 1023;
        int r = j >> 3;
        int u = j & 7;
        const __half* src =
            (s ? ql : qh) + (size_t)(b * LL + q0 + r) * 1024 + h * 64 + (u << 3);
        cp16(smb + s * QSUB + r * AST + (u << 4), src);
    }
    CP_COMMIT();

    // ---- KV pipeline (2 stages of 32 keys, K+V single) ----
    auto pf = [&](int c, int st) {
#pragma unroll
        for (int t = 0; t < 2; t++) {
            int i = tid + (t << 8);            // 0..511
            int s = i >> 8;                    // 0: K, 1: V
            int j = i & 255;
            int r = j >> 3;
            int u = j & 7;
            const __half* src =
                (s ? vh : kh) + (size_t)(b * LL + (c << 5) + r) * 256
                + kvh2 * 64 + (u << 3);
            cp16(smb + KV_OFF + st * KVSTG + s * KVSUB + r * AST + (u << 4), src);
        }
    };
    pf(0, 0); CP_COMMIT();
    pf(1, 1); CP_COMMIT();

    CP_WAIT2();
    __syncthreads();

    const uint32_t qaddr = (uint32_t)((wid * 16 + (lid & 15)) * AST
                                      + ((lid >> 4) << 4));
    uint32_t AQh[4][4];
#pragma unroll
    for (int kt = 0; kt < 4; kt++)
        ldsm4(smb + qaddr + kt * 32, AQh[kt]);

    const uint32_t kaddr = (uint32_t)((((lid >> 4) << 3) + (lid & 7)) * AST
                                      + (((lid >> 3) & 1) << 4));
    const uint32_t vaddr = (uint32_t)((lid & 15) * AST + ((lid >> 4) << 4));

    float o[8][4];
    float lsum[2];
#pragma unroll
    for (int i = 0; i < 8; i++)
#pragma unroll
        for (int e = 0; e < 4; e++) o[i][e] = 0.0f;
    lsum[0] = 0.0f; lsum[1] = 0.0f;

    const int NTILES = LL / 32;   // 64

    for (int c = 0; c < NTILES; c++) {
        CP_WAIT1();
        __syncthreads();

        const uint32_t sb = smb + KV_OFF + (c & 1) * KVSTG;
        const uint32_t sk = sb;
        const uint32_t sv = sb + KVSUB;

        // ---- S = Q.K^T (2-term: Qh.K + Ql.K) ----
        float S[4][4];
#pragma unroll
        for (int i = 0; i < 4; i++)
#pragma unroll
            for (int e = 0; e < 4; e++) S[i][e] = 0.0f;

#pragma unroll
        for (int ks = 0; ks < 4; ks++) {
            uint32_t Ql[4];
            ldsm4(smb + QSUB + qaddr + (ks << 5), Ql);
#pragma unroll
            for (int g = 0; g < 2; g++) {
                uint32_t Kf[4];
                ldsm4(sk + (g << 4) * AST + kaddr + (ks << 5), Kf);
                mma16816(S[2 * g],     AQh[ks], Kf);
                mma16816(S[2 * g],     Ql,      Kf);
                mma16816(S[2 * g + 1], AQh[ks], Kf + 2);
                mma16816(S[2 * g + 1], Ql,      Kf + 2);
            }
        }

        // ---- softmax (analytic max, q-independent bias) ----
        const float bias00 =
            slope * ((float)((c << 5) + 2 * (lid & 3)) - 2047.0f) - 8.0f;
        uint32_t PAh[2][4], PAl[2][4];
#pragma unroll
        for (int nt = 0; nt < 4; nt++) {
            const float be = bias00 + slope * (float)(nt << 3);
            const float bo = be + slope;
            float p0 = __expf(fmaf(S[nt][0], scale, be));
            float p1 = __expf(fmaf(S[nt][1], scale, bo));
            float p2 = __expf(fmaf(S[nt][2], scale, be));
            float p3 = __expf(fmaf(S[nt][3], scale, bo));
            lsum[0] += p0 + p1;
            lsum[1] += p2 + p3;
            S[nt][0] = p0; S[nt][1] = p1;
            S[nt][2] = p2; S[nt][3] = p3;
        }
#pragma unroll
        for (int kt = 0; kt < 2; kt++) {
            float p00 = S[2 * kt][0],     p01 = S[2 * kt][1];
            float p02 = S[2 * kt][2],     p03 = S[2 * kt][3];
            float p10 = S[2 * kt + 1][0], p11 = S[2 * kt + 1][1];
            float p12 = S[2 * kt + 1][2], p13 = S[2 * kt + 1][3];
            float h00 = hhi(p00), h01 = hhi(p01), h02 = hhi(p02), h03 = hhi(p03);
            float h10 = hhi(p10), h11 = hhi(p11), h12 = hhi(p12), h13 = hhi(p13);
            PAh[kt][0] = packh(h00, h01);
            PAh[kt][1] = packh(h02, h03);
            PAh[kt][2] = packh(h10, h11);
            PAh[kt][3] = packh(h12, h13);
            PAl[kt][0] = packh(p00 - h00, p01 - h01);
            PAl[kt][1] = packh(p02 - h02, p03 - h03);
            PAl[kt][2] = packh(p10 - h10, p11 - h11);
            PAl[kt][3] = packh(p12 - h12, p13 - h13);
        }

        // ---- O += P @ V (2-term: Ph.V + Pl.V), V single ----
#pragma unroll
        for (int dg = 0; dg < 4; dg++) {
#pragma unroll
            for (int kt = 0; kt < 2; kt++) {
                uint32_t Vf[4];
                ldsm4t(sv + (kt << 4) * AST + vaddr + (dg << 5), Vf);
                mma16816(o[2 * dg],     PAh[kt], Vf);
                mma16816(o[2 * dg],     PAl[kt], Vf);
                mma16816(o[2 * dg + 1], PAh[kt], Vf + 2);
                mma16816(o[2 * dg + 1], PAl[kt], Vf + 2);
            }
        }

        __syncthreads();
        if (c + 2 < NTILES) pf(c + 2, c & 1);
        CP_COMMIT();
    }

    // ---- epilogue: reduce lsum, normalize, fp16 split to ctx ----
#pragma unroll
    for (int r = 0; r < 2; r++) {
        lsum[r] += __shfl_xor_sync(0xffffffffu, lsum[r], 1);
        lsum[r] += __shfl_xor_sync(0xffffffffu, lsum[r], 2);
    }
    float inv0 = 1.0f / lsum[0];
    float inv1 = 1.0f / lsum[1];
    const int r0 = b * LL + q0 + wid * 16 + (lid >> 2);
#pragma unroll
    for (int nt = 0; nt < 8; nt++) {
        int cc = h * 64 + nt * 8 + ((lid & 3) << 1);
        float v0 = o[nt][0] * inv0, v1 = o[nt][1] * inv0;
        float v2 = o[nt][2] * inv1, v3 = o[nt][3] * inv1;
        float h0 = hhi(v0), h1 = hhi(v1), h2 = hhi(v2), h3 = hhi(v3);
        size_t oa = (size_t)r0 * 1024 + cc;
        size_t ob = (size_t)(r0 + 8) * 1024 + cc;
        *(uint32_t*)&cthi[oa] = packh(h0, h1);
        *(uint32_t*)&ctlo[oa] = packh(v0 - h0, v1 - h1);
        *(uint32_t*)&cthi[ob] = packh(h2, h3);
        *(uint32_t*)&ctlo[ob] = packh(v2 - h2, v3 - h3);
    }
}

// ---------------------------------------------------------------------------
// kernel_launch: 0 prep_x  1 prep_w  2 gemm_qkv  3 attn_mma(capture)  4 gemm_o
// ---------------------------------------------------------------------------
extern "C" void kernel_launch(void* const* d_in, const int* in_sizes, int n_in,
                              void* d_out, int out_size) {
    const float* x  = (const float*)d_in[0];
    const float* Wq = (const float*)d_in[1];
    const float* Wk = (const float*)d_in[2];
    const float* Wv = (const float*)d_in[3];
    const float* Wo = (const float*)d_in[4];
    float* out = (float*)d_out;

    __half *xhi, *xlo, *cthi, *ctlo, *wq, *wkv, *wo;
    __half *aqh, *aql, *akh, *avh;
    float *ct, *st;
    cudaGetSymbolAddress((void**)&xhi,  g_xhi);
    cudaGetSymbolAddress((void**)&xlo,  g_xlo);
    cudaGetSymbolAddress((void**)&cthi, g_ctxhi);
    cudaGetSymbolAddress((void**)&ctlo, g_ctxlo);
    cudaGetSymbolAddress((void**)&wq,   g_wqt);
    cudaGetSymbolAddress((void**)&wkv,  g_wkvt);
    cudaGetSymbolAddress((void**)&wo,   g_wot);
    cudaGetSymbolAddress((void**)&aqh,  g_qh);
    cudaGetSymbolAddress((void**)&aql,  g_ql);
    cudaGetSymbolAddress((void**)&akh,  g_kh);
    cudaGetSymbolAddress((void**)&avh,  g_vh);
    cudaGetSymbolAddress((void**)&ct,   g_cos);
    cudaGetSymbolAddress((void**)&st,   g_sin);

    const int smem_gemm = 2 * STG3;   // 61440
    cudaFuncSetAttribute(gemm_qkv, cudaFuncAttributeMaxDynamicSharedMemorySize,
                         smem_gemm);
    cudaFuncSetAttribute(gemm_o, cudaFuncAttributeMaxDynamicSharedMemorySize,
                         smem_gemm);
    cudaFuncSetAttribute(attn_mma, cudaFuncAttributeMaxDynamicSharedMemorySize,
                         ATT_SMEM);

    dim3 blk(256);

    // 0: x split + rope tables
    prep_x<<<4096 + 256, blk>>>(x, xhi, xlo, ct, st);
    // 1: weight transposes (single fp16)
    prep_w<<<2560, blk>>>(Wq, Wk, Wv, Wo, wq, wkv, wo);

    // 2: QKV projection (fp16 2-term) + fused RoPE/split epilogue
    gemm_qkv<<<dim3(12, BL / 128), blk, smem_gemm>>>(
        xhi, xlo, wq, wkv, aqh, aql, akh, avh, ct, st);

    // 3: attention (fp16 2-term)  <-- capture slot
    attn_mma<<<dim3(LL / 128, HH, BB), blk, ATT_SMEM>>>(
        aqh, aql, akh, avh, cthi, ctlo);

    // 4: output projection (fp16 2-term)
    gemm_o<<<dim3(8, BL / 128), blk, smem_gemm>>>(
        cthi, ctlo, wo, out, DD, DD);
}

// round 17
// speedup vs baseline: 1.9396x; 1.2931x over previous
#include <cuda_runtime.h>
#include <cuda_fp16.h>
#include <math.h>
#include <stdint.h>

// Problem constants
#define BB   2
#define LL   2048
#define DD   1024
#define HH   16
#define KVH  4
#define HDIM 64
#define BL   (BB * LL)    // 4096

typedef unsigned long long ull;

// ---------------------------------------------------------------------------
// mma.sync / ldmatrix / cp.async helpers (baseline PTX ISA)
// ---------------------------------------------------------------------------
__device__ __forceinline__ uint32_t smem_u32(const void* p) {
    uint32_t a;
    asm("{ .reg .u64 t; cvta.to.shared.u64 t, %1; cvt.u32.u64 %0, t; }"
        : "=r"(a) : "l"(p));
    return a;
}
__device__ __forceinline__ void ldsm4(uint32_t addr, uint32_t* r) {
    asm volatile("ldmatrix.sync.aligned.m8n8.x4.shared.b16 {%0,%1,%2,%3}, [%4];"
                 : "=r"(r[0]), "=r"(r[1]), "=r"(r[2]), "=r"(r[3]) : "r"(addr));
}
__device__ __forceinline__ void ldsm4t(uint32_t addr, uint32_t* r) {
    asm volatile("ldmatrix.sync.aligned.m8n8.x4.trans.shared.b16 {%0,%1,%2,%3}, [%4];"
                 : "=r"(r[0]), "=r"(r[1]), "=r"(r[2]), "=r"(r[3]) : "r"(addr));
}
__device__ __forceinline__ void mma16816(float* d, const uint32_t* a,
                                         const uint32_t* b) {
    asm volatile(
        "mma.sync.aligned.m16n8k16.row.col.f32.f16.f16.f32 "
        "{%0,%1,%2,%3}, {%4,%5,%6,%7}, {%8,%9}, {%0,%1,%2,%3};"
        : "+f"(d[0]), "+f"(d[1]), "+f"(d[2]), "+f"(d[3])
        : "r"(a[0]), "r"(a[1]), "r"(a[2]), "r"(a[3]), "r"(b[0]), "r"(b[1]));
}
__device__ __forceinline__ void cp16(uint32_t dst, const void* src) {
    asm volatile("cp.async.cg.shared.global [%0], [%1], 16;"
                 :: "r"(dst), "l"(src) : "memory");
}
#define CP_COMMIT() asm volatile("cp.async.commit_group;" ::: "memory")
#define CP_WAIT2()  asm volatile("cp.async.wait_group 2;" ::: "memory")
#define CP_WAIT1()  asm volatile("cp.async.wait_group 1;" ::: "memory")

__device__ __forceinline__ uint32_t packh(float a, float b) {
    __half2 t = __floats2half2_rn(a, b);
    return *(uint32_t*)&t;
}
__device__ __forceinline__ float hhi(float v) {
    return __half2float(__float2half(v));
}

// ---------------------------------------------------------------------------
// Scratch (__device__ globals — no allocations allowed)
// ---------------------------------------------------------------------------
__device__ __half g_xhi[BL * DD];
__device__ __half g_xlo[BL * DD];
__device__ __half g_ctxhi[BL * DD];
__device__ __half g_ctxlo[BL * DD];
__device__ __half g_wqt[DD * DD];
__device__ __half g_wkvt[512 * DD];
__device__ __half g_wot[DD * DD];

__device__ __half g_qh[BL * DD];        // Q single fp16
__device__ __half g_kh[BL * 256];       // K single
__device__ __half g_vh[BL * 256];       // V single

__device__ float g_cos[LL * 32];
__device__ float g_sin[LL * 32];

// ---------------------------------------------------------------------------
// prep_x: x fp32 -> fp16 hi/lo split + rope tables
// ---------------------------------------------------------------------------
__global__ __launch_bounds__(256)
void prep_x(const float* __restrict__ x,
            __half* __restrict__ xhi, __half* __restrict__ xlo,
            float* __restrict__ ct, float* __restrict__ st) {
    const int bid = blockIdx.x;
    if (bid < 4096) {
        int i = bid * 256 + threadIdx.x;
        float4 v = ((const float4*)x)[i];
        float vv[4] = {v.x, v.y, v.z, v.w};
        __half h[4], l[4];
#pragma unroll
        for (int j = 0; j < 4; j++) {
            h[j] = __float2half(vv[j]);
            l[j] = __float2half(vv[j] - __half2float(h[j]));
        }
        ((uint64_t*)xhi)[i] = *(uint64_t*)h;
        ((uint64_t*)xlo)[i] = *(uint64_t*)l;
    } else {
        int i = (bid - 4096) * 256 + threadIdx.x;
        int pos = i >> 5, j = i & 31;
        float inv = powf(10000.0f, -(float)j * (1.0f / 32.0f));
        float s, c;
        sincosf((float)pos * inv, &s, &c);
        ct[i] = c;
        st[i] = s;
    }
}

// ---------------------------------------------------------------------------
// prep_w: weight transposes -> single fp16
// ---------------------------------------------------------------------------
__global__ __launch_bounds__(256)
void prep_w(const float* __restrict__ Wq, const float* __restrict__ Wk,
            const float* __restrict__ Wv, const float* __restrict__ Wo,
            __half* __restrict__ wq, __half* __restrict__ wkv,
            __half* __restrict__ wo) {
    __shared__ float t[32][33];
    int j = blockIdx.x;
    const float* W;
    __half* outT;
    int Nd, rowoff = 0, bx, by;
    if (j < 1024) { W = Wq; outT = wq; Nd = 1024;
                    bx = j & 31; by = j >> 5; }
    else if (j < 1536) {
        int j2 = j - 1024;
        int z = j2 >> 8;
        int r = j2 & 255;
        bx = r & 7; by = r >> 3;
        Nd = 256;
        outT = wkv;
        if (z == 0) { W = Wk; }
        else        { W = Wv; rowoff = 256; }
    } else {
        int j2 = j - 1536;
        W = Wo; outT = wo; Nd = 1024;
        bx = j2 & 31; by = j2 >> 5;
    }
    int n0 = bx << 5, k0 = by << 5;
    int tx = threadIdx.x & 31, ty = threadIdx.x >> 5;
    for (int r = ty; r < 32; r += 8)
        t[r][tx] = W[(size_t)(k0 + r) * Nd + n0 + tx];
    __syncthreads();
    for (int r = ty; r < 32; r += 8)
        outT[(size_t)(rowoff + n0 + r) * DD + k0 + tx] = __float2half(t[tx][r]);
}

#define SUB3 10240
#define STG3 30720

// ---------------------------------------------------------------------------
// QKV GEMM (fp16 2-term A, single B) with fused RoPE; Q/K/V all single fp16.
// ---------------------------------------------------------------------------
__global__ __launch_bounds__(256, 2)
void gemm_qkv(const __half* __restrict__ Ahi, const __half* __restrict__ Alo,
              const __half* __restrict__ Wq, const __half* __restrict__ Wkv,
              __half* __restrict__ qh, __half* __restrict__ kh,
              __half* __restrict__ vh,
              const float* __restrict__ ct, const float* __restrict__ st) {
    extern __shared__ char sm[];
    const uint32_t smb = smem_u32(sm);
    const int K = DD;

    const int tid = threadIdx.x;
    const int lid = tid & 31;
    const int wid = tid >> 5;
    const int wm  = wid >> 1;
    const int wn  = wid & 1;
    const int row0 = blockIdx.y << 7;
    const int NCH = K >> 5;

    const bool isQ = (int)blockIdx.x < 8;
    const int col0 = isQ ? (blockIdx.x << 7) : (((int)blockIdx.x - 8) << 7);
    const __half* B = isQ ? Wq : Wkv;

    const __half* srcbase[3] = {Ahi, Alo, B};

    auto prefetch = [&](int c, int stage) {
#pragma unroll
        for (int it = 0; it < 6; it++) {
            int i = tid + (it << 8);
            int s = i >> 9;
            int j = i & 511;
            int r = j >> 2;
            int u = j & 3;
            int grow = (s < 2 ? row0 : col0) + r;
            const __half* src =
                srcbase[s] + (size_t)grow * K + (c << 5) + (u << 3);
            uint32_t dst = smb + stage * STG3 + s * SUB3 + r * 80 + (u << 4);
            cp16(dst, src);
        }
    };

    prefetch(0, 0); CP_COMMIT();
    prefetch(1, 1); CP_COMMIT();

    float acc[2][8][4];
#pragma unroll
    for (int a = 0; a < 2; a++)
#pragma unroll
        for (int b = 0; b < 8; b++)
#pragma unroll
            for (int d = 0; d < 4; d++) acc[a][b][d] = 0.0f;

    const uint32_t aoff = (uint32_t)((wm * 32 + (lid & 15)) * 80
                                     + ((lid >> 4) << 4));
    const uint32_t boff = (uint32_t)((wn * 64 + ((lid >> 4) << 3) + (lid & 7)) * 80
                                     + (((lid >> 3) & 1) << 4));

    for (int c = 0; c < NCH; c++) {
        CP_WAIT1();
        __syncthreads();

        const uint32_t sb = smb + (c & 1) * STG3;
        const uint32_t sa_h = sb;
        const uint32_t sa_l = sb + SUB3;
        const uint32_t sb_b = sb + 2 * SUB3;

#pragma unroll
        for (int ks = 0; ks < 2; ks++) {
            uint32_t Ah[2][4], Al[2][4];
            ldsm4(sa_h + aoff + ks * 32, Ah[0]);
            ldsm4(sa_h + aoff + 16 * 80 + ks * 32, Ah[1]);
            ldsm4(sa_l + aoff + ks * 32, Al[0]);
            ldsm4(sa_l + aoff + 16 * 80 + ks * 32, Al[1]);
#pragma unroll
            for (int g = 0; g < 4; g++) {
                uint32_t Bf[4];
                ldsm4(sb_b + boff + g * (16 * 80) + ks * 32, Bf);
#pragma unroll
                for (int mi = 0; mi < 2; mi++) {
                    mma16816(acc[mi][2 * g],     Ah[mi], Bf);
                    mma16816(acc[mi][2 * g],     Al[mi], Bf);
                    mma16816(acc[mi][2 * g + 1], Ah[mi], Bf + 2);
                    mma16816(acc[mi][2 * g + 1], Al[mi], Bf + 2);
                }
            }
        }
        __syncthreads();
        if (c + 2 < NCH) prefetch(c + 2, c & 1);
        CP_COMMIT();
    }

    // ---- fused epilogue: RoPE (Q,K) -> single fp16 outputs ----
    const int rbase = row0 + wm * 32 + (lid >> 2);
    const int mode = isQ ? 0 : (col0 < 256 ? 1 : 2);   // 0:Q 1:K 2:V
    const int ldd = isQ ? 1024 : 256;
    const int dcol0 = (mode == 2) ? col0 - 256 : col0;
    __half* dst = (mode == 0) ? qh : (mode == 1 ? kh : vh);

#pragma unroll
    for (int mi = 0; mi < 2; mi++) {
#pragma unroll
        for (int half = 0; half < 2; half++) {
            const int row = rbase + mi * 16 + half * 8;
            const int pos = row & (LL - 1);
            const int e0 = half * 2;
            if (mode == 2) {   // V: no rope
#pragma unroll
                for (int ni = 0; ni < 8; ni++) {
                    const int j0 = ni * 8 + ((lid & 3) << 1);
                    size_t o1 = (size_t)row * ldd + dcol0 + wn * 64 + j0;
                    *(uint32_t*)&dst[o1] =
                        packh(acc[mi][ni][e0], acc[mi][ni][e0 + 1]);
                }
            } else {           // Q or K: rope, single fp16
#pragma unroll
                for (int ni = 0; ni < 4; ni++) {
                    const int j0 = ni * 8 + ((lid & 3) << 1);
                    float c0 = ct[pos * 32 + j0],     s0 = st[pos * 32 + j0];
                    float c1 = ct[pos * 32 + j0 + 1], s1 = st[pos * 32 + j0 + 1];
                    float x1a = acc[mi][ni][e0],     x1b = acc[mi][ni][e0 + 1];
                    float x2a = acc[mi][ni + 4][e0], x2b = acc[mi][ni + 4][e0 + 1];
                    float y1a = x1a * c0 - x2a * s0;
                    float y2a = x2a * c0 + x1a * s0;
                    float y1b = x1b * c1 - x2b * s1;
                    float y2b = x2b * c1 + x1b * s1;
                    size_t o1 = (size_t)row * ldd + dcol0 + wn * 64 + j0;
                    size_t o2 = o1 + 32;
                    *(uint32_t*)&dst[o1] = packh(y1a, y1b);
                    *(uint32_t*)&dst[o2] = packh(y2a, y2b);
                }
            }
        }
    }
}

// ---------------------------------------------------------------------------
// Output projection GEMM: A = ctx hi/lo fp16, B = Wo single fp16, fp32 out.
// ---------------------------------------------------------------------------
__global__ __launch_bounds__(256, 2)
void gemm_o(const __half* __restrict__ Ahi, const __half* __restrict__ Alo,
            const __half* __restrict__ B, float* __restrict__ C,
            int K, int ldc) {
    extern __shared__ char sm[];
    const uint32_t smb = smem_u32(sm);

    const int tid = threadIdx.x;
    const int lid = tid & 31;
    const int wid = tid >> 5;
    const int wm  = wid >> 1;
    const int wn  = wid & 1;
    const int row0 = blockIdx.y << 7;
    const int col0 = blockIdx.x << 7;
    const int NCH = K >> 5;

    const __half* srcbase[3] = {Ahi, Alo, B};

    auto prefetch = [&](int c, int stage) {
#pragma unroll
        for (int it = 0; it < 6; it++) {
            int i = tid + (it << 8);
            int s = i >> 9;
            int j = i & 511;
            int r = j >> 2;
            int u = j & 3;
            int grow = (s < 2 ? row0 : col0) + r;
            const __half* src =
                srcbase[s] + (size_t)grow * K + (c << 5) + (u << 3);
            uint32_t dst = smb + stage * STG3 + s * SUB3 + r * 80 + (u << 4);
            cp16(dst, src);
        }
    };

    prefetch(0, 0); CP_COMMIT();
    prefetch(1, 1); CP_COMMIT();

    float acc[2][8][4];
#pragma unroll
    for (int a = 0; a < 2; a++)
#pragma unroll
        for (int b = 0; b < 8; b++)
#pragma unroll
            for (int d = 0; d < 4; d++) acc[a][b][d] = 0.0f;

    const uint32_t aoff = (uint32_t)((wm * 32 + (lid & 15)) * 80
                                     + ((lid >> 4) << 4));
    const uint32_t boff = (uint32_t)((wn * 64 + ((lid >> 4) << 3) + (lid & 7)) * 80
                                     + (((lid >> 3) & 1) << 4));

    for (int c = 0; c < NCH; c++) {
        CP_WAIT1();
        __syncthreads();

        const uint32_t sb = smb + (c & 1) * STG3;
        const uint32_t sa_h = sb;
        const uint32_t sa_l = sb + SUB3;
        const uint32_t sb_b = sb + 2 * SUB3;

#pragma unroll
        for (int ks = 0; ks < 2; ks++) {
            uint32_t Ah[2][4], Al[2][4];
            ldsm4(sa_h + aoff + ks * 32, Ah[0]);
            ldsm4(sa_h + aoff + 16 * 80 + ks * 32, Ah[1]);
            ldsm4(sa_l + aoff + ks * 32, Al[0]);
            ldsm4(sa_l + aoff + 16 * 80 + ks * 32, Al[1]);
#pragma unroll
            for (int g = 0; g < 4; g++) {
                uint32_t Bf[4];
                ldsm4(sb_b + boff + g * (16 * 80) + ks * 32, Bf);
#pragma unroll
                for (int mi = 0; mi < 2; mi++) {
                    mma16816(acc[mi][2 * g],     Ah[mi], Bf);
                    mma16816(acc[mi][2 * g],     Al[mi], Bf);
                    mma16816(acc[mi][2 * g + 1], Ah[mi], Bf + 2);
                    mma16816(acc[mi][2 * g + 1], Al[mi], Bf + 2);
                }
            }
        }
        __syncthreads();
        if (c + 2 < NCH) prefetch(c + 2, c & 1);
        CP_COMMIT();
    }

#pragma unroll
    for (int mi = 0; mi < 2; mi++) {
        int r0 = row0 + wm * 32 + mi * 16 + (lid >> 2);
#pragma unroll
        for (int ni = 0; ni < 8; ni++) {
            int cc = col0 + wn * 64 + ni * 8 + ((lid & 3) << 1);
            float2 v0; v0.x = acc[mi][ni][0]; v0.y = acc[mi][ni][1];
            float2 v1; v1.x = acc[mi][ni][2]; v1.y = acc[mi][ni][3];
            *(float2*)(C + (size_t)r0 * ldc + cc)       = v0;
            *(float2*)(C + (size_t)(r0 + 8) * ldc + cc) = v1;
        }
    }
}

// ---------------------------------------------------------------------------
// Flash attention, ALL-single fp16 MMAs (Q, K, P, V single; fp32 accum).
// 128 q-rows/CTA, 32-key tiles, 2-stage pipeline, occ 2, analytic-max softmax.
// smem: Q 18432 + 2*(K 4608 + V 4608) = 36864.
// ---------------------------------------------------------------------------
#define AST 144
#define KVSUB (32 * AST)           // 4608
#define KVSTG (2 * KVSUB)          // 9216
#define QSUB  (128 * AST)          // 18432
#define ATT_SMEM (QSUB + 2 * KVSTG)   // 36864

__global__ __launch_bounds__(256, 2)
void attn_mma(const __half* __restrict__ qh,
              const __half* __restrict__ kh, const __half* __restrict__ vh,
              __half* __restrict__ cthi, __half* __restrict__ ctlo) {
    extern __shared__ char sm[];
    const uint32_t smb = smem_u32(sm);

    const int tid = threadIdx.x;
    const int lid = tid & 31;
    const int wid = tid >> 5;
    const int q0  = blockIdx.x << 7;
    const int h   = blockIdx.y;
    const int b   = blockIdx.z;
    const int kvh2 = h >> 2;

    const float slope = exp2f(-0.5f * (float)(h + 1));
    const float scale = 0.125f;

    // ---- stage Q (single) into permanent smem ----
#pragma unroll
    for (int t = 0; t < 4; t++) {
        int i = tid + (t << 8);                // 0..1023
        int r = i >> 3;
        int u = i & 7;
        const __half* src =
            qh + (size_t)(b * LL + q0 + r) * 1024 + h * 64 + (u << 3);
        cp16(smb + r * AST + (u << 4), src);
    }
    CP_COMMIT();

    // ---- KV pipeline (2 stages of 32 keys, single) ----
    auto pf = [&](int c, int st) {
#pragma unroll
        for (int t = 0; t < 2; t++) {
            int i = tid + (t << 8);
            int s = i >> 8;
            int j = i & 255;
            int r = j >> 3;
            int u = j & 7;
            const __half* src =
                (s ? vh : kh) + (size_t)(b * LL + (c << 5) + r) * 256
                + kvh2 * 64 + (u << 3);
            cp16(smb + QSUB + st * KVSTG + s * KVSUB + r * AST + (u << 4), src);
        }
    };
    pf(0, 0); CP_COMMIT();
    pf(1, 1); CP_COMMIT();

    CP_WAIT2();
    __syncthreads();

    const uint32_t qaddr = (uint32_t)((wid * 16 + (lid & 15)) * AST
                                      + ((lid >> 4) << 4));
    uint32_t AQ[4][4];
#pragma unroll
    for (int kt = 0; kt < 4; kt++)
        ldsm4(smb + qaddr + kt * 32, AQ[kt]);

    const uint32_t kaddr = (uint32_t)((((lid >> 4) << 3) + (lid & 7)) * AST
                                      + (((lid >> 3) & 1) << 4));
    const uint32_t vaddr = (uint32_t)((lid & 15) * AST + ((lid >> 4) << 4));

    float o[8][4];
    float lsum[2];
#pragma unroll
    for (int i = 0; i < 8; i++)
#pragma unroll
        for (int e = 0; e < 4; e++) o[i][e] = 0.0f;
    lsum[0] = 0.0f; lsum[1] = 0.0f;

    const int NTILES = LL / 32;   // 64

    for (int c = 0; c < NTILES; c++) {
        CP_WAIT1();
        __syncthreads();

        const uint32_t sb = smb + QSUB + (c & 1) * KVSTG;
        const uint32_t sk = sb;
        const uint32_t sv = sb + KVSUB;

        // ---- S = Q.K^T (single x single) ----
        float S[4][4];
#pragma unroll
        for (int i = 0; i < 4; i++)
#pragma unroll
            for (int e = 0; e < 4; e++) S[i][e] = 0.0f;

#pragma unroll
        for (int ks = 0; ks < 4; ks++) {
#pragma unroll
            for (int g = 0; g < 2; g++) {
                uint32_t Kf[4];
                ldsm4(sk + (g << 4) * AST + kaddr + (ks << 5), Kf);
                mma16816(S[2 * g],     AQ[ks], Kf);
                mma16816(S[2 * g + 1], AQ[ks], Kf + 2);
            }
        }

        // ---- softmax (analytic max, q-independent bias) ----
        const float bias00 =
            slope * ((float)((c << 5) + 2 * (lid & 3)) - 2047.0f) - 8.0f;
        uint32_t PA[2][4];
#pragma unroll
        for (int nt = 0; nt < 4; nt++) {
            const float be = bias00 + slope * (float)(nt << 3);
            const float bo = be + slope;
            float p0 = __expf(fmaf(S[nt][0], scale, be));
            float p1 = __expf(fmaf(S[nt][1], scale, bo));
            float p2 = __expf(fmaf(S[nt][2], scale, be));
            float p3 = __expf(fmaf(S[nt][3], scale, bo));
            lsum[0] += p0 + p1;
            lsum[1] += p2 + p3;
            S[nt][0] = p0; S[nt][1] = p1;
            S[nt][2] = p2; S[nt][3] = p3;
        }
#pragma unroll
        for (int kt = 0; kt < 2; kt++) {
            PA[kt][0] = packh(S[2 * kt][0],     S[2 * kt][1]);
            PA[kt][1] = packh(S[2 * kt][2],     S[2 * kt][3]);
            PA[kt][2] = packh(S[2 * kt + 1][0], S[2 * kt + 1][1]);
            PA[kt][3] = packh(S[2 * kt + 1][2], S[2 * kt + 1][3]);
        }

        // ---- O += P @ V (single x single) ----
#pragma unroll
        for (int dg = 0; dg < 4; dg++) {
#pragma unroll
            for (int kt = 0; kt < 2; kt++) {
                uint32_t Vf[4];
                ldsm4t(sv + (kt << 4) * AST + vaddr + (dg << 5), Vf);
                mma16816(o[2 * dg],     PA[kt], Vf);
                mma16816(o[2 * dg + 1], PA[kt], Vf + 2);
            }
        }

        __syncthreads();
        if (c + 2 < NTILES) pf(c + 2, c & 1);
        CP_COMMIT();
    }

    // ---- epilogue: reduce lsum, normalize, fp16 split to ctx ----
#pragma unroll
    for (int r = 0; r < 2; r++) {
        lsum[r] += __shfl_xor_sync(0xffffffffu, lsum[r], 1);
        lsum[r] += __shfl_xor_sync(0xffffffffu, lsum[r], 2);
    }
    float inv0 = 1.0f / lsum[0];
    float inv1 = 1.0f / lsum[1];
    const int r0 = b * LL + q0 + wid * 16 + (lid >> 2);
#pragma unroll
    for (int nt = 0; nt < 8; nt++) {
        int cc = h * 64 + nt * 8 + ((lid & 3) << 1);
        float v0 = o[nt][0] * inv0, v1 = o[nt][1] * inv0;
        float v2 = o[nt][2] * inv1, v3 = o[nt][3] * inv1;
        float h0 = hhi(v0), h1 = hhi(v1), h2 = hhi(v2), h3 = hhi(v3);
        size_t oa = (size_t)r0 * 1024 + cc;
        size_t ob = (size_t)(r0 + 8) * 1024 + cc;
        *(uint32_t*)&cthi[oa] = packh(h0, h1);
        *(uint32_t*)&ctlo[oa] = packh(v0 - h0, v1 - h1);
        *(uint32_t*)&cthi[ob] = packh(h2, h3);
        *(uint32_t*)&ctlo[ob] = packh(v2 - h2, v3 - h3);
    }
}

// ---------------------------------------------------------------------------
// kernel_launch: 0 prep_x  1 prep_w  2 gemm_qkv  3 attn_mma(capture)  4 gemm_o
// ---------------------------------------------------------------------------
extern "C" void kernel_launch(void* const* d_in, const int* in_sizes, int n_in,
                              void* d_out, int out_size) {
    const float* x  = (const float*)d_in[0];
    const float* Wq = (const float*)d_in[1];
    const float* Wk = (const float*)d_in[2];
    const float* Wv = (const float*)d_in[3];
    const float* Wo = (const float*)d_in[4];
    float* out = (float*)d_out;

    __half *xhi, *xlo, *cthi, *ctlo, *wq, *wkv, *wo;
    __half *aqh, *akh, *avh;
    float *ct, *st;
    cudaGetSymbolAddress((void**)&xhi,  g_xhi);
    cudaGetSymbolAddress((void**)&xlo,  g_xlo);
    cudaGetSymbolAddress((void**)&cthi, g_ctxhi);
    cudaGetSymbolAddress((void**)&ctlo, g_ctxlo);
    cudaGetSymbolAddress((void**)&wq,   g_wqt);
    cudaGetSymbolAddress((void**)&wkv,  g_wkvt);
    cudaGetSymbolAddress((void**)&wo,   g_wot);
    cudaGetSymbolAddress((void**)&aqh,  g_qh);
    cudaGetSymbolAddress((void**)&akh,  g_kh);
    cudaGetSymbolAddress((void**)&avh,  g_vh);
    cudaGetSymbolAddress((void**)&ct,   g_cos);
    cudaGetSymbolAddress((void**)&st,   g_sin);

    const int smem_gemm = 2 * STG3;
    cudaFuncSetAttribute(gemm_qkv, cudaFuncAttributeMaxDynamicSharedMemorySize,
                         smem_gemm);
    cudaFuncSetAttribute(gemm_o, cudaFuncAttributeMaxDynamicSharedMemorySize,
                         smem_gemm);
    cudaFuncSetAttribute(attn_mma, cudaFuncAttributeMaxDynamicSharedMemorySize,
                         ATT_SMEM);

    dim3 blk(256);

    // 0: x split + rope tables
    prep_x<<<4096 + 256, blk>>>(x, xhi, xlo, ct, st);
    // 1: weight transposes (single fp16)
    prep_w<<<2560, blk>>>(Wq, Wk, Wv, Wo, wq, wkv, wo);

    // 2: QKV projection (fp16 2-term) + fused RoPE; Q/K/V single fp16
    gemm_qkv<<<dim3(12, BL / 128), blk, smem_gemm>>>(
        xhi, xlo, wq, wkv, aqh, akh, avh, ct, st);

    // 3: attention (all-single fp16 MMAs)  <-- capture slot
    attn_mma<<<dim3(LL / 128, HH, BB), blk, ATT_SMEM>>>(
        aqh, akh, avh, cthi, ctlo);

    // 4: output projection (fp16 2-term)
    gemm_o<<<dim3(8, BL / 128), blk, smem_gemm>>>(
        cthi, ctlo, wo, out, DD, DD);
}